// round 1
// baseline (speedup 1.0000x reference)
#include <cuda_runtime.h>
#include <cuda_bf16.h>

// Problem constants (fixed by the reference):
//   B=2, C=512, H=W=64 -> N=4096, GROUPS=32 (16 ch/group), EPS=1e-6
// Inputs (d_in order): x, gn_w, gn_b, wq, bq, wk, bk, wv, bv, wo, bo
// Output: x + Wo @ Attn(GN(x)) + bo, layout [B,C,H,W] fp32.

#define BATCH 2
#define CCH   512
#define NPIX  4096
#define GROUPS 32
#define GEPS  1e-6f

static const long long CN = (long long)CCH * NPIX;        // 2M elements
static const long long NN = (long long)NPIX * NPIX;       // 16M elements

// Scratch (device globals; no allocation allowed)
__device__ float g_h[BATCH * CCH * NPIX];
__device__ float g_q[BATCH * CCH * NPIX];
__device__ float g_k[BATCH * CCH * NPIX];
__device__ float g_v[BATCH * CCH * NPIX];
__device__ float g_o[BATCH * CCH * NPIX];
__device__ float g_attn[(long long)BATCH * NPIX * NPIX];  // 134 MB

// ---------------------------------------------------------------------------
// GroupNorm: one block per (batch, group). Each group = 16 ch * 4096 px =
// 65536 contiguous floats in [B,C,N] layout.
// ---------------------------------------------------------------------------
__global__ __launch_bounds__(256) void groupnorm_kernel(
    const float* __restrict__ x, const float* __restrict__ w,
    const float* __restrict__ b, float* __restrict__ h)
{
    const int bg = blockIdx.x;                 // b*32 + g
    const long long base = (long long)bg * 65536;
    const int t = threadIdx.x;

    float s = 0.f, ss = 0.f;
    #pragma unroll 8
    for (int i = t; i < 65536; i += 256) {
        float v = x[base + i];
        s += v; ss += v * v;
    }
    // warp reduce
    #pragma unroll
    for (int off = 16; off; off >>= 1) {
        s  += __shfl_down_sync(0xffffffffu, s,  off);
        ss += __shfl_down_sync(0xffffffffu, ss, off);
    }
    __shared__ float shs[8], shss[8], stat[2];
    int wid = t >> 5, lane = t & 31;
    if (lane == 0) { shs[wid] = s; shss[wid] = ss; }
    __syncthreads();
    if (t == 0) {
        float ts = 0.f, tss = 0.f;
        #pragma unroll
        for (int i = 0; i < 8; i++) { ts += shs[i]; tss += shss[i]; }
        float mean = ts * (1.f / 65536.f);
        float var  = tss * (1.f / 65536.f) - mean * mean;
        stat[0] = mean;
        stat[1] = rsqrtf(var + GEPS);
    }
    __syncthreads();
    const float mean = stat[0], inv = stat[1];
    const int c0 = (bg & 31) * 16;
    #pragma unroll 4
    for (int i = t; i < 65536; i += 256) {
        int c = c0 + (i >> 12);
        h[base + i] = (x[base + i] - mean) * inv * w[c] + b[c];
    }
}

// ---------------------------------------------------------------------------
// Generic fp32 tiled GEMM: C = alpha * op(A) * op(B) (+bias[m]) (+res)
//   AT=0: A is [M,K] row-major (A[m*lda+k]); AT=1: A is [K,M] (A[k*lda+m])
//   BT=0: B is [K,N] row-major (B[k*ldb+n]); BT=1: B is [N,K] (B[n*ldb+k])
// Tiles: BM=BN=128, BK=16, 256 threads, 8x8 per thread.
// All of M,N divisible by 128, K divisible by 16 -> no bounds checks.
// blockIdx.z = batch; per-batch strides sA/sB/sC/sR.
// ---------------------------------------------------------------------------
#define TBM 128
#define TBN 128
#define TBK 16

template<int AT, int BT, bool BIAS, bool RES>
__global__ __launch_bounds__(256) void gemm_kernel(
    const float* __restrict__ A, const float* __restrict__ B,
    float* __restrict__ C,
    const float* __restrict__ bias, const float* __restrict__ res,
    int M, int N, int K, int lda, int ldb, int ldc,
    long long sA, long long sB, long long sC, long long sR, float alpha)
{
    __shared__ float As[TBK][TBM];
    __shared__ float Bs[TBK][TBN];

    const int t  = threadIdx.x;
    const int tx = t & 15;        // 16 cols of threads
    const int ty = t >> 4;        // 16 rows of threads
    const int m0 = blockIdx.y * TBM;
    const int n0 = blockIdx.x * TBN;

    A += (long long)blockIdx.z * sA;
    B += (long long)blockIdx.z * sB;
    C += (long long)blockIdx.z * sC;
    const float* R = RES ? (res + (long long)blockIdx.z * sR) : nullptr;

    float acc[8][8];
    #pragma unroll
    for (int i = 0; i < 8; i++)
        #pragma unroll
        for (int j = 0; j < 8; j++) acc[i][j] = 0.f;

    for (int k0 = 0; k0 < K; k0 += TBK) {
        // ---- load A tile into As[k][m] ----
        if (AT == 0) {
            #pragma unroll
            for (int it = 0; it < 2; it++) {
                int idx = t + it * 256;          // 0..511 float4 slots
                int m   = idx >> 2;              // 0..127
                int k4  = (idx & 3) * 4;
                float4 va = *(const float4*)&A[(long long)(m0 + m) * lda + k0 + k4];
                As[k4 + 0][m] = va.x; As[k4 + 1][m] = va.y;
                As[k4 + 2][m] = va.z; As[k4 + 3][m] = va.w;
            }
        } else {
            #pragma unroll
            for (int it = 0; it < 2; it++) {
                int idx = t + it * 256;
                int k   = idx >> 5;              // 0..15
                int m4  = (idx & 31) * 4;
                *(float4*)&As[k][m4] =
                    *(const float4*)&A[(long long)(k0 + k) * lda + m0 + m4];
            }
        }
        // ---- load B tile into Bs[k][n] ----
        if (BT == 0) {
            #pragma unroll
            for (int it = 0; it < 2; it++) {
                int idx = t + it * 256;
                int k   = idx >> 5;
                int n4  = (idx & 31) * 4;
                *(float4*)&Bs[k][n4] =
                    *(const float4*)&B[(long long)(k0 + k) * ldb + n0 + n4];
            }
        } else {
            #pragma unroll
            for (int it = 0; it < 2; it++) {
                int idx = t + it * 256;
                int n   = idx >> 2;
                int k4  = (idx & 3) * 4;
                float4 vb = *(const float4*)&B[(long long)(n0 + n) * ldb + k0 + k4];
                Bs[k4 + 0][n] = vb.x; Bs[k4 + 1][n] = vb.y;
                Bs[k4 + 2][n] = vb.z; Bs[k4 + 3][n] = vb.w;
            }
        }
        __syncthreads();

        #pragma unroll
        for (int k = 0; k < TBK; k++) {
            float4 a0 = *(const float4*)&As[k][ty * 8];
            float4 a1 = *(const float4*)&As[k][ty * 8 + 4];
            float4 b0 = *(const float4*)&Bs[k][tx * 8];
            float4 b1 = *(const float4*)&Bs[k][tx * 8 + 4];
            float av[8] = {a0.x, a0.y, a0.z, a0.w, a1.x, a1.y, a1.z, a1.w};
            float bv[8] = {b0.x, b0.y, b0.z, b0.w, b1.x, b1.y, b1.z, b1.w};
            #pragma unroll
            for (int i = 0; i < 8; i++)
                #pragma unroll
                for (int j = 0; j < 8; j++)
                    acc[i][j] += av[i] * bv[j];
        }
        __syncthreads();
    }

    // ---- epilogue ----
    #pragma unroll
    for (int i = 0; i < 8; i++) {
        int m = m0 + ty * 8 + i;
        float bi = BIAS ? bias[m] : 0.f;
        #pragma unroll
        for (int j = 0; j < 8; j += 4) {
            long long off = (long long)m * ldc + n0 + tx * 8 + j;
            float4 v;
            v.x = acc[i][j + 0] * alpha + bi;
            v.y = acc[i][j + 1] * alpha + bi;
            v.z = acc[i][j + 2] * alpha + bi;
            v.w = acc[i][j + 3] * alpha + bi;
            if (RES) {
                float4 r = *(const float4*)&R[off];
                v.x += r.x; v.y += r.y; v.z += r.z; v.w += r.w;
            }
            *(float4*)&C[off] = v;
        }
    }
}

// ---------------------------------------------------------------------------
// Row softmax over attn rows of length 4096. One block (256 thr) per row;
// 16 values per thread held in registers -> single global read + write.
// ---------------------------------------------------------------------------
__global__ __launch_bounds__(256) void softmax_kernel(float* __restrict__ attn)
{
    float* p = attn + (long long)blockIdx.x * NPIX;
    const int t = threadIdx.x;
    float v[16];
    float mx = -1e30f;
    #pragma unroll
    for (int i = 0; i < 16; i++) {
        v[i] = p[t + i * 256];
        mx = fmaxf(mx, v[i]);
    }
    // block max
    #pragma unroll
    for (int off = 16; off; off >>= 1)
        mx = fmaxf(mx, __shfl_xor_sync(0xffffffffu, mx, off));
    __shared__ float sh[8];
    __shared__ float blk[2];
    int wid = t >> 5, lane = t & 31;
    if (lane == 0) sh[wid] = mx;
    __syncthreads();
    if (t == 0) {
        float m = sh[0];
        #pragma unroll
        for (int i = 1; i < 8; i++) m = fmaxf(m, sh[i]);
        blk[0] = m;
    }
    __syncthreads();
    mx = blk[0];

    float s = 0.f;
    #pragma unroll
    for (int i = 0; i < 16; i++) {
        v[i] = __expf(v[i] - mx);
        s += v[i];
    }
    #pragma unroll
    for (int off = 16; off; off >>= 1)
        s += __shfl_xor_sync(0xffffffffu, s, off);
    if (lane == 0) sh[wid] = s;
    __syncthreads();
    if (t == 0) {
        float tot = 0.f;
        #pragma unroll
        for (int i = 0; i < 8; i++) tot += sh[i];
        blk[1] = 1.f / tot;
    }
    __syncthreads();
    const float inv = blk[1];
    #pragma unroll
    for (int i = 0; i < 16; i++)
        p[t + i * 256] = v[i] * inv;
}

// ---------------------------------------------------------------------------
// Launch
// ---------------------------------------------------------------------------
extern "C" void kernel_launch(void* const* d_in, const int* in_sizes, int n_in,
                              void* d_out, int out_size)
{
    const float* x    = (const float*)d_in[0];
    const float* gn_w = (const float*)d_in[1];
    const float* gn_b = (const float*)d_in[2];
    const float* wq   = (const float*)d_in[3];
    const float* bq   = (const float*)d_in[4];
    const float* wk   = (const float*)d_in[5];
    const float* bk   = (const float*)d_in[6];
    const float* wv   = (const float*)d_in[7];
    const float* bv   = (const float*)d_in[8];
    const float* wo   = (const float*)d_in[9];
    const float* bo   = (const float*)d_in[10];
    float* out = (float*)d_out;

    float *h, *q, *k, *v, *o, *attn;
    cudaGetSymbolAddress((void**)&h,    g_h);
    cudaGetSymbolAddress((void**)&q,    g_q);
    cudaGetSymbolAddress((void**)&k,    g_k);
    cudaGetSymbolAddress((void**)&v,    g_v);
    cudaGetSymbolAddress((void**)&o,    g_o);
    cudaGetSymbolAddress((void**)&attn, g_attn);

    const float scale = 0.044194173824159216f;  // 512^-0.5

    // 1) GroupNorm
    groupnorm_kernel<<<BATCH * GROUPS, 256>>>(x, gn_w, gn_b, h);

    // 2) q/k/v projections: [512x512] @ [512x4096] + bias, per batch
    dim3 gProj(NPIX / TBN, CCH / TBM, BATCH);   // 32 x 4 x 2
    gemm_kernel<0, 0, true, false><<<gProj, 256>>>(
        wq, h, q, bq, nullptr, CCH, NPIX, CCH, CCH, NPIX, NPIX,
        0, CN, CN, 0, 1.0f);
    gemm_kernel<0, 0, true, false><<<gProj, 256>>>(
        wk, h, k, bk, nullptr, CCH, NPIX, CCH, CCH, NPIX, NPIX,
        0, CN, CN, 0, 1.0f);
    gemm_kernel<0, 0, true, false><<<gProj, 256>>>(
        wv, h, v, bv, nullptr, CCH, NPIX, CCH, CCH, NPIX, NPIX,
        0, CN, CN, 0, 1.0f);

    // 3) S = scale * Q^T K : [4096x4096], K-dim = 512 channels
    dim3 gS(NPIX / TBN, NPIX / TBM, BATCH);     // 32 x 32 x 2
    gemm_kernel<1, 0, false, false><<<gS, 256>>>(
        q, k, attn, nullptr, nullptr, NPIX, NPIX, CCH, NPIX, NPIX, NPIX,
        CN, CN, NN, 0, scale);

    // 4) row softmax over j
    softmax_kernel<<<BATCH * NPIX, 256>>>(attn);

    // 5) O = V @ P^T : [512x4096], K-dim = 4096 tokens
    dim3 gAV(NPIX / TBN, CCH / TBM, BATCH);
    gemm_kernel<0, 1, false, false><<<gAV, 256>>>(
        v, attn, o, nullptr, nullptr, CCH, NPIX, NPIX, NPIX, NPIX, NPIX,
        CN, NN, CN, 0, 1.0f);

    // 6) out = x + Wo @ O + bo
    gemm_kernel<0, 0, true, true><<<gProj, 256>>>(
        wo, o, out, bo, x, CCH, NPIX, CCH, CCH, NPIX, NPIX,
        0, CN, CN, CN, 1.0f);
}

// round 2
// speedup vs baseline: 2.9087x; 2.9087x over previous
#include <cuda_runtime.h>
#include <cuda_bf16.h>
#include <cstdint>

// B=2, C=512, H=W=64 -> N=4096, GROUPS=32 (16 ch/grp), EPS=1e-6
// out = x + Wo @ Attn(GN(x)) + bo  in [B,C,H,W] fp32
#define BATCH 2
#define CCH   512
#define NPIX  4096
#define GEPS  1e-6f

static const long long CN = (long long)CCH * NPIX;
static const long long NN = (long long)NPIX * NPIX;

__device__ float g_h[BATCH * CCH * NPIX];
__device__ float g_q[BATCH * CCH * NPIX];
__device__ float g_k[BATCH * CCH * NPIX];
__device__ float g_v[BATCH * CCH * NPIX];
__device__ float g_o[BATCH * CCH * NPIX];
__device__ float g_attn[(long long)BATCH * NPIX * NPIX];

// ---------------------------------------------------------------------------
// helpers
// ---------------------------------------------------------------------------
__device__ __forceinline__ uint32_t f2tf32(float f) {
    uint32_t u;
    asm("cvt.rna.tf32.f32 %0, %1;" : "=r"(u) : "f"(f));
    return u;
}
__device__ __forceinline__ void mma_tf32(float c[4],
    uint32_t a0, uint32_t a1, uint32_t a2, uint32_t a3,
    uint32_t b0, uint32_t b1)
{
    asm volatile(
        "mma.sync.aligned.m16n8k8.row.col.f32.tf32.tf32.f32 "
        "{%0,%1,%2,%3},{%4,%5,%6,%7},{%8,%9},{%0,%1,%2,%3};"
        : "+f"(c[0]), "+f"(c[1]), "+f"(c[2]), "+f"(c[3])
        : "r"(a0), "r"(a1), "r"(a2), "r"(a3), "r"(b0), "r"(b1));
}
__device__ __forceinline__ void cpasync16(uint32_t s, const void* g) {
    asm volatile("cp.async.cg.shared.global [%0], [%1], 16;" :: "r"(s), "l"(g));
}
__device__ __forceinline__ uint32_t smem_u32(const void* p) {
    return (uint32_t)__cvta_generic_to_shared(p);
}

// ---------------------------------------------------------------------------
// GroupNorm
// ---------------------------------------------------------------------------
__global__ __launch_bounds__(256) void groupnorm_kernel(
    const float* __restrict__ x, const float* __restrict__ w,
    const float* __restrict__ b, float* __restrict__ h)
{
    const int bg = blockIdx.x;
    const long long base = (long long)bg * 65536;
    const int t = threadIdx.x;

    float s = 0.f, ss = 0.f;
    #pragma unroll 8
    for (int i = t; i < 65536; i += 256) {
        float v = x[base + i];
        s += v; ss += v * v;
    }
    #pragma unroll
    for (int off = 16; off; off >>= 1) {
        s  += __shfl_down_sync(0xffffffffu, s,  off);
        ss += __shfl_down_sync(0xffffffffu, ss, off);
    }
    __shared__ float shs[8], shss[8], stat[2];
    int wid = t >> 5, lane = t & 31;
    if (lane == 0) { shs[wid] = s; shss[wid] = ss; }
    __syncthreads();
    if (t == 0) {
        float ts = 0.f, tss = 0.f;
        #pragma unroll
        for (int i = 0; i < 8; i++) { ts += shs[i]; tss += shss[i]; }
        float mean = ts * (1.f / 65536.f);
        float var  = tss * (1.f / 65536.f) - mean * mean;
        stat[0] = mean; stat[1] = rsqrtf(var + GEPS);
    }
    __syncthreads();
    const float mean = stat[0], inv = stat[1];
    const int c0 = (bg & 31) * 16;
    #pragma unroll 4
    for (int i = t; i < 65536; i += 256) {
        int c = c0 + (i >> 12);
        h[base + i] = (x[base + i] - mean) * inv * w[c] + b[c];
    }
}

// ---------------------------------------------------------------------------
// TF32 tensor-core GEMM: C = alpha*op(A)*op(B) (+bias[m]) (+res)
//   AT=0: A[m][k] row-major; AT=1: A[k][m]
//   BT=0: B[k][n];           BT=1: B[n][k]
// Block tile 128x128xBK16, 256 thr = 8 warps (2x4), warp tile 64x32.
// mma.sync m16n8k8 tf32 with cvt.rna on fragment load. cp.async 2-stage.
// All dims multiples of tile sizes -> no predication.
// ---------------------------------------------------------------------------
#define TBM 128
#define TBN 128
#define TBK 16

template<int AT, int BT, bool BIAS, bool RES>
__global__ __launch_bounds__(256) void gemm_tc(
    const float* __restrict__ A, const float* __restrict__ B,
    float* __restrict__ C,
    const float* __restrict__ bias, const float* __restrict__ res,
    int K, int lda, int ldb, int ldc,
    long long sA, long long sB, long long sC, long long sR, float alpha)
{
    // smem layouts chosen so cp.async 16B chunks land contiguously and the
    // fragment LDS pattern is bank-conflict-free:
    //   [k][x] layout: row stride TBM+8 (=136) -> banks 8*tig+g (32 distinct)
    //   [x][k] layout: row stride TBK+4 (=20)  -> banks 20*g+tig (32 distinct)
    constexpr int AR = AT ? TBK : TBM;
    constexpr int AC = AT ? (TBM + 8) : (TBK + 4);
    constexpr int BR = BT ? TBN : TBK;
    constexpr int BC = BT ? (TBK + 4) : (TBN + 8);
    __shared__ float sAm[2][AR][AC];
    __shared__ float sBm[2][BR][BC];

    const int t    = threadIdx.x;
    const int wid  = t >> 5;
    const int lane = t & 31;
    const int g    = lane >> 2;     // 0..7
    const int tig  = lane & 3;      // 0..3
    const int m_w  = (wid >> 2) * 64;
    const int n_w  = (wid & 3) * 32;
    const int m0   = blockIdx.y * TBM;
    const int n0   = blockIdx.x * TBN;

    A += (long long)blockIdx.z * sA;
    B += (long long)blockIdx.z * sB;
    C += (long long)blockIdx.z * sC;
    const float* R = RES ? (res + (long long)blockIdx.z * sR) : nullptr;

    float acc[4][4][4];
    #pragma unroll
    for (int i = 0; i < 4; i++)
        #pragma unroll
        for (int j = 0; j < 4; j++)
            #pragma unroll
            for (int r = 0; r < 4; r++) acc[i][j][r] = 0.f;

    const int nk = K / TBK;

    // stage loader: 512 float4 for A, 512 for B, 256 threads -> 2+2 each
    auto load_stage = [&](int ks, int buf) {
        const int k0 = ks * TBK;
        #pragma unroll
        for (int it = 0; it < 2; it++) {
            int slot = t + it * 256;
            if (AT == 0) {
                int m = slot >> 2, kq = (slot & 3) * 4;
                cpasync16(smem_u32(&sAm[buf][m][kq]),
                          &A[(long long)(m0 + m) * lda + k0 + kq]);
            } else {
                int k = slot >> 5, mq = (slot & 31) * 4;
                cpasync16(smem_u32(&sAm[buf][k][mq]),
                          &A[(long long)(k0 + k) * lda + m0 + mq]);
            }
        }
        #pragma unroll
        for (int it = 0; it < 2; it++) {
            int slot = t + it * 256;
            if (BT == 0) {
                int k = slot >> 5, nq = (slot & 31) * 4;
                cpasync16(smem_u32(&sBm[buf][k][nq]),
                          &B[(long long)(k0 + k) * ldb + n0 + nq]);
            } else {
                int n = slot >> 2, kq = (slot & 3) * 4;
                cpasync16(smem_u32(&sBm[buf][n][kq]),
                          &B[(long long)(n0 + n) * ldb + k0 + kq]);
            }
        }
    };

    load_stage(0, 0);
    asm volatile("cp.async.commit_group;");

    #pragma unroll 1
    for (int ks = 0; ks < nk; ks++) {
        const int buf = ks & 1;
        if (ks + 1 < nk) {
            load_stage(ks + 1, (ks + 1) & 1);
            asm volatile("cp.async.commit_group;");
            asm volatile("cp.async.wait_group 1;");
        } else {
            asm volatile("cp.async.wait_group 0;");
        }
        __syncthreads();

        #pragma unroll
        for (int kk = 0; kk < TBK; kk += 8) {
            uint32_t af[4][4];
            #pragma unroll
            for (int i = 0; i < 4; i++) {
                int mr = m_w + 16 * i + g;
                if (AT == 0) {
                    af[i][0] = f2tf32(sAm[buf][mr    ][kk + tig    ]);
                    af[i][1] = f2tf32(sAm[buf][mr + 8][kk + tig    ]);
                    af[i][2] = f2tf32(sAm[buf][mr    ][kk + tig + 4]);
                    af[i][3] = f2tf32(sAm[buf][mr + 8][kk + tig + 4]);
                } else {
                    af[i][0] = f2tf32(sAm[buf][kk + tig    ][mr    ]);
                    af[i][1] = f2tf32(sAm[buf][kk + tig    ][mr + 8]);
                    af[i][2] = f2tf32(sAm[buf][kk + tig + 4][mr    ]);
                    af[i][3] = f2tf32(sAm[buf][kk + tig + 4][mr + 8]);
                }
            }
            uint32_t bf[4][2];
            #pragma unroll
            for (int j = 0; j < 4; j++) {
                int nc = n_w + 8 * j + g;
                if (BT == 0) {
                    bf[j][0] = f2tf32(sBm[buf][kk + tig    ][nc]);
                    bf[j][1] = f2tf32(sBm[buf][kk + tig + 4][nc]);
                } else {
                    bf[j][0] = f2tf32(sBm[buf][nc][kk + tig    ]);
                    bf[j][1] = f2tf32(sBm[buf][nc][kk + tig + 4]);
                }
            }
            #pragma unroll
            for (int i = 0; i < 4; i++)
                #pragma unroll
                for (int j = 0; j < 4; j++)
                    mma_tf32(acc[i][j], af[i][0], af[i][1], af[i][2], af[i][3],
                             bf[j][0], bf[j][1]);
        }
        __syncthreads();
    }

    // epilogue: c0,c1 -> row g, cols 2tig,2tig+1 ; c2,c3 -> row g+8
    #pragma unroll
    for (int i = 0; i < 4; i++) {
        int r0 = m0 + m_w + 16 * i + g;
        int r1 = r0 + 8;
        float bi0 = BIAS ? bias[r0] : 0.f;
        float bi1 = BIAS ? bias[r1] : 0.f;
        #pragma unroll
        for (int j = 0; j < 4; j++) {
            long long cc = (long long)(n0 + n_w + 8 * j + 2 * tig);
            long long o0 = (long long)r0 * ldc + cc;
            long long o1 = (long long)r1 * ldc + cc;
            float2 v0, v1;
            v0.x = acc[i][j][0] * alpha + bi0;
            v0.y = acc[i][j][1] * alpha + bi0;
            v1.x = acc[i][j][2] * alpha + bi1;
            v1.y = acc[i][j][3] * alpha + bi1;
            if (RES) {
                float2 r0v = *(const float2*)&R[o0];
                float2 r1v = *(const float2*)&R[o1];
                v0.x += r0v.x; v0.y += r0v.y;
                v1.x += r1v.x; v1.y += r1v.y;
            }
            *(float2*)&C[o0] = v0;
            *(float2*)&C[o1] = v1;
        }
    }
}

// ---------------------------------------------------------------------------
// Row softmax over 4096-length rows
// ---------------------------------------------------------------------------
__global__ __launch_bounds__(256) void softmax_kernel(float* __restrict__ attn)
{
    float* p = attn + (long long)blockIdx.x * NPIX;
    const int t = threadIdx.x;
    float v[16];
    float mx = -1e30f;
    #pragma unroll
    for (int i = 0; i < 16; i++) {
        v[i] = p[t + i * 256];
        mx = fmaxf(mx, v[i]);
    }
    #pragma unroll
    for (int off = 16; off; off >>= 1)
        mx = fmaxf(mx, __shfl_xor_sync(0xffffffffu, mx, off));
    __shared__ float sh[8];
    __shared__ float blk[2];
    int wid = t >> 5, lane = t & 31;
    if (lane == 0) sh[wid] = mx;
    __syncthreads();
    if (t == 0) {
        float m = sh[0];
        #pragma unroll
        for (int i = 1; i < 8; i++) m = fmaxf(m, sh[i]);
        blk[0] = m;
    }
    __syncthreads();
    mx = blk[0];

    float s = 0.f;
    #pragma unroll
    for (int i = 0; i < 16; i++) {
        v[i] = __expf(v[i] - mx);
        s += v[i];
    }
    #pragma unroll
    for (int off = 16; off; off >>= 1)
        s += __shfl_xor_sync(0xffffffffu, s, off);
    if (lane == 0) sh[wid] = s;
    __syncthreads();
    if (t == 0) {
        float tot = 0.f;
        #pragma unroll
        for (int i = 0; i < 8; i++) tot += sh[i];
        blk[1] = 1.f / tot;
    }
    __syncthreads();
    const float inv = blk[1];
    #pragma unroll
    for (int i = 0; i < 16; i++)
        p[t + i * 256] = v[i] * inv;
}

// ---------------------------------------------------------------------------
extern "C" void kernel_launch(void* const* d_in, const int* in_sizes, int n_in,
                              void* d_out, int out_size)
{
    const float* x    = (const float*)d_in[0];
    const float* gn_w = (const float*)d_in[1];
    const float* gn_b = (const float*)d_in[2];
    const float* wq   = (const float*)d_in[3];
    const float* bq   = (const float*)d_in[4];
    const float* wk   = (const float*)d_in[5];
    const float* bk   = (const float*)d_in[6];
    const float* wv   = (const float*)d_in[7];
    const float* bv   = (const float*)d_in[8];
    const float* wo   = (const float*)d_in[9];
    const float* bo   = (const float*)d_in[10];
    float* out = (float*)d_out;

    float *h, *q, *k, *v, *o, *attn;
    cudaGetSymbolAddress((void**)&h,    g_h);
    cudaGetSymbolAddress((void**)&q,    g_q);
    cudaGetSymbolAddress((void**)&k,    g_k);
    cudaGetSymbolAddress((void**)&v,    g_v);
    cudaGetSymbolAddress((void**)&o,    g_o);
    cudaGetSymbolAddress((void**)&attn, g_attn);

    const float scale = 0.044194173824159216f;  // 512^-0.5

    groupnorm_kernel<<<BATCH * 32, 256>>>(x, gn_w, gn_b, h);

    // q/k/v projections: W[512x512] @ h[512x4096] + bias
    dim3 gProj(NPIX / TBN, CCH / TBM, BATCH);
    gemm_tc<0, 0, true, false><<<gProj, 256>>>(
        wq, h, q, bq, nullptr, CCH, CCH, NPIX, NPIX, 0, CN, CN, 0, 1.0f);
    gemm_tc<0, 0, true, false><<<gProj, 256>>>(
        wk, h, k, bk, nullptr, CCH, CCH, NPIX, NPIX, 0, CN, CN, 0, 1.0f);
    gemm_tc<0, 0, true, false><<<gProj, 256>>>(
        wv, h, v, bv, nullptr, CCH, CCH, NPIX, NPIX, 0, CN, CN, 0, 1.0f);

    // S = scale * Q^T K  [4096x4096], K-dim 512
    dim3 gS(NPIX / TBN, NPIX / TBM, BATCH);
    gemm_tc<1, 0, false, false><<<gS, 256>>>(
        q, k, attn, nullptr, nullptr, CCH, NPIX, NPIX, NPIX,
        CN, CN, NN, 0, scale);

    softmax_kernel<<<BATCH * NPIX, 256>>>(attn);

    // O = V @ P^T  [512x4096], K-dim 4096
    dim3 gAV(NPIX / TBN, CCH / TBM, BATCH);
    gemm_tc<0, 1, false, false><<<gAV, 256>>>(
        v, attn, o, nullptr, nullptr, NPIX, NPIX, NPIX, NPIX,
        CN, NN, CN, 0, 1.0f);

    // out = x + Wo @ O + bo
    gemm_tc<0, 0, true, true><<<gProj, 256>>>(
        wo, o, out, bo, x, CCH, CCH, NPIX, NPIX, 0, CN, CN, CN, 1.0f);
}

// round 3
// speedup vs baseline: 3.0283x; 1.0411x over previous
#include <cuda_runtime.h>
#include <cuda_bf16.h>
#include <cstdint>

// B=2, C=512, H=W=64 -> N=4096, GROUPS=32 (16 ch/grp), EPS=1e-6
// out = x + Wo @ Attn(GN(x)) + bo  in [B,C,H,W] fp32
#define BATCH 2
#define CCH   512
#define NPIX  4096
#define GEPS  1e-6f

static const long long CN = (long long)CCH * NPIX;      // 2M
static const long long NN = (long long)NPIX * NPIX;     // 16M

__device__ float g_h[BATCH * CCH * NPIX];
__device__ float g_qkv[(long long)BATCH * 3 * CCH * NPIX];   // [B][q,k,v][C][N]
__device__ float g_o[BATCH * CCH * NPIX];
__device__ float g_attn[(long long)BATCH * NPIX * NPIX];
__device__ float g_wr[4 * CCH * CCH];                        // rounded wq,wk,wv,wo

// ---------------------------------------------------------------------------
// helpers
// ---------------------------------------------------------------------------
__device__ __forceinline__ float round_tf32(float f) {
    uint32_t u;
    asm("cvt.rna.tf32.f32 %0, %1;" : "=r"(u) : "f"(f));
    return __uint_as_float(u);
}
__device__ __forceinline__ void mma_tf32(float c[4],
    float a0, float a1, float a2, float a3, float b0, float b1)
{
    asm volatile(
        "mma.sync.aligned.m16n8k8.row.col.f32.tf32.tf32.f32 "
        "{%0,%1,%2,%3},{%4,%5,%6,%7},{%8,%9},{%0,%1,%2,%3};"
        : "+f"(c[0]), "+f"(c[1]), "+f"(c[2]), "+f"(c[3])
        : "r"(__float_as_uint(a0)), "r"(__float_as_uint(a1)),
          "r"(__float_as_uint(a2)), "r"(__float_as_uint(a3)),
          "r"(__float_as_uint(b0)), "r"(__float_as_uint(b1)));
}
__device__ __forceinline__ void cpasync16(uint32_t s, const void* g) {
    asm volatile("cp.async.cg.shared.global [%0], [%1], 16;" :: "r"(s), "l"(g));
}
__device__ __forceinline__ uint32_t smem_u32(const void* p) {
    return (uint32_t)__cvta_generic_to_shared(p);
}

// ---------------------------------------------------------------------------
// One-shot TF32 rounding of the 4 weight matrices into g_wr
// ---------------------------------------------------------------------------
__global__ __launch_bounds__(256) void round_weights_kernel(
    const float* __restrict__ wq, const float* __restrict__ wk,
    const float* __restrict__ wv, const float* __restrict__ wo,
    float* __restrict__ dst)
{
    const int idx = blockIdx.x * 256 + threadIdx.x;        // float4 index
    const int per = CCH * CCH / 4;                         // 65536
    const int which = idx / per;
    const int off = (idx - which * per) * 4;
    const float* src = which == 0 ? wq : which == 1 ? wk : which == 2 ? wv : wo;
    float4 v = *(const float4*)&src[off];
    v.x = round_tf32(v.x); v.y = round_tf32(v.y);
    v.z = round_tf32(v.z); v.w = round_tf32(v.w);
    *(float4*)&dst[(long long)which * CCH * CCH + off] = v;
}

// ---------------------------------------------------------------------------
// GroupNorm (stores TF32-pre-rounded h)
// ---------------------------------------------------------------------------
__global__ __launch_bounds__(256) void groupnorm_kernel(
    const float* __restrict__ x, const float* __restrict__ w,
    const float* __restrict__ b, float* __restrict__ h)
{
    const int bg = blockIdx.x;
    const long long base = (long long)bg * 65536;
    const int t = threadIdx.x;

    float s = 0.f, ss = 0.f;
    #pragma unroll 8
    for (int i = t; i < 65536; i += 256) {
        float v = x[base + i];
        s += v; ss += v * v;
    }
    #pragma unroll
    for (int off = 16; off; off >>= 1) {
        s  += __shfl_down_sync(0xffffffffu, s,  off);
        ss += __shfl_down_sync(0xffffffffu, ss, off);
    }
    __shared__ float shs[8], shss[8], stat[2];
    int wid = t >> 5, lane = t & 31;
    if (lane == 0) { shs[wid] = s; shss[wid] = ss; }
    __syncthreads();
    if (t == 0) {
        float ts = 0.f, tss = 0.f;
        #pragma unroll
        for (int i = 0; i < 8; i++) { ts += shs[i]; tss += shss[i]; }
        float mean = ts * (1.f / 65536.f);
        float var  = tss * (1.f / 65536.f) - mean * mean;
        stat[0] = mean; stat[1] = rsqrtf(var + GEPS);
    }
    __syncthreads();
    const float mean = stat[0], inv = stat[1];
    const int c0 = (bg & 31) * 16;
    #pragma unroll 4
    for (int i = t; i < 65536; i += 256) {
        int c = c0 + (i >> 12);
        h[base + i] = round_tf32((x[base + i] - mean) * inv * w[c] + b[c]);
    }
}

// ---------------------------------------------------------------------------
// TF32 tensor-core GEMM core (inputs pre-rounded to tf32; no cvt inside).
//   AT=0: A[m][k]; AT=1: A[k][m].  BT=0: B[k][n]; BT=1: B[n][k]
// Block tile 128x128x16, 8 warps (2x4), warp tile 64x32, m16n8k8.
// OUTR: round outputs to tf32 before store (for GEMM-feeding buffers).
// ---------------------------------------------------------------------------
#define TBM 128
#define TBN 128
#define TBK 16

template<int AT, int BT, bool BIAS, bool RES, bool OUTR>
__device__ __forceinline__ void gemm_body(
    const float* __restrict__ A, const float* __restrict__ B,
    float* __restrict__ C,
    const float* __restrict__ bias, const float* __restrict__ R,
    int K, int lda, int ldb, int ldc,
    int m0, int n0, float alpha)
{
    constexpr int AR = AT ? TBK : TBM;
    constexpr int AC = AT ? (TBM + 8) : (TBK + 4);
    constexpr int BR = BT ? TBN : TBK;
    constexpr int BC = BT ? (TBK + 4) : (TBN + 8);
    __shared__ float sAm[2][AR][AC];
    __shared__ float sBm[2][BR][BC];

    const int t    = threadIdx.x;
    const int wid  = t >> 5;
    const int lane = t & 31;
    const int g    = lane >> 2;
    const int tig  = lane & 3;
    const int m_w  = (wid >> 2) * 64;
    const int n_w  = (wid & 3) * 32;

    float acc[4][4][4];
    #pragma unroll
    for (int i = 0; i < 4; i++)
        #pragma unroll
        for (int j = 0; j < 4; j++)
            #pragma unroll
            for (int r = 0; r < 4; r++) acc[i][j][r] = 0.f;

    const int nk = K / TBK;

    auto load_stage = [&](int ks, int buf) {
        const int k0 = ks * TBK;
        #pragma unroll
        for (int it = 0; it < 2; it++) {
            int slot = t + it * 256;
            if (AT == 0) {
                int m = slot >> 2, kq = (slot & 3) * 4;
                cpasync16(smem_u32(&sAm[buf][m][kq]),
                          &A[(long long)(m0 + m) * lda + k0 + kq]);
            } else {
                int k = slot >> 5, mq = (slot & 31) * 4;
                cpasync16(smem_u32(&sAm[buf][k][mq]),
                          &A[(long long)(k0 + k) * lda + m0 + mq]);
            }
        }
        #pragma unroll
        for (int it = 0; it < 2; it++) {
            int slot = t + it * 256;
            if (BT == 0) {
                int k = slot >> 5, nq = (slot & 31) * 4;
                cpasync16(smem_u32(&sBm[buf][k][nq]),
                          &B[(long long)(k0 + k) * ldb + n0 + nq]);
            } else {
                int n = slot >> 2, kq = (slot & 3) * 4;
                cpasync16(smem_u32(&sBm[buf][n][kq]),
                          &B[(long long)(n0 + n) * ldb + k0 + kq]);
            }
        }
    };

    load_stage(0, 0);
    asm volatile("cp.async.commit_group;");

    #pragma unroll 1
    for (int ks = 0; ks < nk; ks++) {
        const int buf = ks & 1;
        if (ks + 1 < nk) {
            load_stage(ks + 1, (ks + 1) & 1);
            asm volatile("cp.async.commit_group;");
            asm volatile("cp.async.wait_group 1;");
        } else {
            asm volatile("cp.async.wait_group 0;");
        }
        __syncthreads();

        #pragma unroll
        for (int kk = 0; kk < TBK; kk += 8) {
            float af[4][4];
            #pragma unroll
            for (int i = 0; i < 4; i++) {
                int mr = m_w + 16 * i + g;
                if (AT == 0) {
                    af[i][0] = sAm[buf][mr    ][kk + tig    ];
                    af[i][1] = sAm[buf][mr + 8][kk + tig    ];
                    af[i][2] = sAm[buf][mr    ][kk + tig + 4];
                    af[i][3] = sAm[buf][mr + 8][kk + tig + 4];
                } else {
                    af[i][0] = sAm[buf][kk + tig    ][mr    ];
                    af[i][1] = sAm[buf][kk + tig    ][mr + 8];
                    af[i][2] = sAm[buf][kk + tig + 4][mr    ];
                    af[i][3] = sAm[buf][kk + tig + 4][mr + 8];
                }
            }
            float bf[4][2];
            #pragma unroll
            for (int j = 0; j < 4; j++) {
                int nc = n_w + 8 * j + g;
                if (BT == 0) {
                    bf[j][0] = sBm[buf][kk + tig    ][nc];
                    bf[j][1] = sBm[buf][kk + tig + 4][nc];
                } else {
                    bf[j][0] = sBm[buf][nc][kk + tig    ];
                    bf[j][1] = sBm[buf][nc][kk + tig + 4];
                }
            }
            #pragma unroll
            for (int i = 0; i < 4; i++)
                #pragma unroll
                for (int j = 0; j < 4; j++)
                    mma_tf32(acc[i][j], af[i][0], af[i][1], af[i][2], af[i][3],
                             bf[j][0], bf[j][1]);
        }
        __syncthreads();
    }

    #pragma unroll
    for (int i = 0; i < 4; i++) {
        int r0 = m0 + m_w + 16 * i + g;
        int r1 = r0 + 8;
        float bi0 = BIAS ? bias[r0] : 0.f;
        float bi1 = BIAS ? bias[r1] : 0.f;
        #pragma unroll
        for (int j = 0; j < 4; j++) {
            long long cc = (long long)(n0 + n_w + 8 * j + 2 * tig);
            long long o0 = (long long)r0 * ldc + cc;
            long long o1 = (long long)r1 * ldc + cc;
            float2 v0, v1;
            v0.x = acc[i][j][0] * alpha + bi0;
            v0.y = acc[i][j][1] * alpha + bi0;
            v1.x = acc[i][j][2] * alpha + bi1;
            v1.y = acc[i][j][3] * alpha + bi1;
            if (RES) {
                float2 r0v = *(const float2*)&R[o0];
                float2 r1v = *(const float2*)&R[o1];
                v0.x += r0v.x; v0.y += r0v.y;
                v1.x += r1v.x; v1.y += r1v.y;
            }
            if (OUTR) {
                v0.x = round_tf32(v0.x); v0.y = round_tf32(v0.y);
                v1.x = round_tf32(v1.x); v1.y = round_tf32(v1.y);
            }
            *(float2*)&C[o0] = v0;
            *(float2*)&C[o1] = v1;
        }
    }
}

template<int AT, int BT, bool BIAS, bool RES, bool OUTR>
__global__ __launch_bounds__(256, 2) void gemm_tc(
    const float* __restrict__ A, const float* __restrict__ B,
    float* __restrict__ C,
    const float* __restrict__ bias, const float* __restrict__ res,
    int K, int lda, int ldb, int ldc,
    long long sA, long long sB, long long sC, long long sR, float alpha)
{
    gemm_body<AT, BT, BIAS, RES, OUTR>(
        A + (long long)blockIdx.z * sA,
        B + (long long)blockIdx.z * sB,
        C + (long long)blockIdx.z * sC,
        bias, RES ? res + (long long)blockIdx.z * sR : nullptr,
        K, lda, ldb, ldc,
        blockIdx.y * TBM, blockIdx.x * TBN, alpha);
}

// Fused QKV projection: blockIdx.y in [0,12): sel = y>>2 (q/k/v), tile = y&3.
// Output layout [B][q,k,v][C][N] in g_qkv. Stores tf32-rounded.
__global__ __launch_bounds__(256, 2) void gemm_qkv(
    const float* __restrict__ wr,          // g_wr: rounded wq,wk,wv
    const float* __restrict__ h,
    float* __restrict__ qkv,
    const float* __restrict__ bq, const float* __restrict__ bk,
    const float* __restrict__ bv)
{
    const int sel = blockIdx.y >> 2;
    const float* A = wr + (long long)sel * CCH * CCH;
    const float* bias = sel == 0 ? bq : sel == 1 ? bk : bv;
    gemm_body<0, 0, true, false, true>(
        A,
        h + (long long)blockIdx.z * CN,
        qkv + ((long long)blockIdx.z * 3 + sel) * CN,
        bias, nullptr,
        CCH, CCH, NPIX, NPIX,
        (blockIdx.y & 3) * TBM, blockIdx.x * TBN, 1.0f);
}

// ---------------------------------------------------------------------------
// Row softmax over 4096-length rows; outputs tf32-rounded probabilities.
// ---------------------------------------------------------------------------
__global__ __launch_bounds__(256) void softmax_kernel(float* __restrict__ attn)
{
    float* p = attn + (long long)blockIdx.x * NPIX;
    const int t = threadIdx.x;
    float v[16];
    float mx = -1e30f;
    #pragma unroll
    for (int i = 0; i < 16; i++) {
        v[i] = p[t + i * 256];
        mx = fmaxf(mx, v[i]);
    }
    #pragma unroll
    for (int off = 16; off; off >>= 1)
        mx = fmaxf(mx, __shfl_xor_sync(0xffffffffu, mx, off));
    __shared__ float sh[8];
    __shared__ float blk[2];
    int wid = t >> 5, lane = t & 31;
    if (lane == 0) sh[wid] = mx;
    __syncthreads();
    if (t == 0) {
        float m = sh[0];
        #pragma unroll
        for (int i = 1; i < 8; i++) m = fmaxf(m, sh[i]);
        blk[0] = m;
    }
    __syncthreads();
    mx = blk[0];

    float s = 0.f;
    #pragma unroll
    for (int i = 0; i < 16; i++) {
        v[i] = __expf(v[i] - mx);
        s += v[i];
    }
    #pragma unroll
    for (int off = 16; off; off >>= 1)
        s += __shfl_xor_sync(0xffffffffu, s, off);
    if (lane == 0) sh[wid] = s;
    __syncthreads();
    if (t == 0) {
        float tot = 0.f;
        #pragma unroll
        for (int i = 0; i < 8; i++) tot += sh[i];
        blk[1] = 1.f / tot;
    }
    __syncthreads();
    const float inv = blk[1];
    #pragma unroll
    for (int i = 0; i < 16; i++)
        p[t + i * 256] = round_tf32(v[i] * inv);
}

// ---------------------------------------------------------------------------
extern "C" void kernel_launch(void* const* d_in, const int* in_sizes, int n_in,
                              void* d_out, int out_size)
{
    const float* x    = (const float*)d_in[0];
    const float* gn_w = (const float*)d_in[1];
    const float* gn_b = (const float*)d_in[2];
    const float* wq   = (const float*)d_in[3];
    const float* bq   = (const float*)d_in[4];
    const float* wk   = (const float*)d_in[5];
    const float* bk   = (const float*)d_in[6];
    const float* wv   = (const float*)d_in[7];
    const float* bv   = (const float*)d_in[8];
    const float* wo   = (const float*)d_in[9];
    const float* bo   = (const float*)d_in[10];
    float* out = (float*)d_out;

    float *h, *qkv, *o, *attn, *wr;
    cudaGetSymbolAddress((void**)&h,    g_h);
    cudaGetSymbolAddress((void**)&qkv,  g_qkv);
    cudaGetSymbolAddress((void**)&o,    g_o);
    cudaGetSymbolAddress((void**)&attn, g_attn);
    cudaGetSymbolAddress((void**)&wr,   g_wr);

    const float scale = 0.044194173824159216f;  // 512^-0.5
    const long long QKV_S = 3 * CN;             // batch stride in g_qkv

    // 0) round weights to tf32 once per launch (deterministic)
    round_weights_kernel<<<4 * CCH * CCH / 4 / 256, 256>>>(wq, wk, wv, wo, wr);

    // 1) GroupNorm (tf32-rounded h)
    groupnorm_kernel<<<BATCH * 32, 256>>>(x, gn_w, gn_b, h);

    // 2) fused q/k/v projection
    dim3 gQKV(NPIX / TBN, 12, BATCH);
    gemm_qkv<<<gQKV, 256>>>(wr, h, qkv, bq, bk, bv);

    // 3) S = scale * Q^T K  [4096x4096] (raw fp32 scores)
    const float* qb = qkv;
    const float* kb = qkv + CN;
    const float* vb = qkv + 2 * CN;
    dim3 gS(NPIX / TBN, NPIX / TBM, BATCH);
    gemm_tc<1, 0, false, false, false><<<gS, 256>>>(
        qb, kb, attn, nullptr, nullptr, CCH, NPIX, NPIX, NPIX,
        QKV_S, QKV_S, NN, 0, scale);

    // 4) softmax (tf32-rounded probs)
    softmax_kernel<<<BATCH * NPIX, 256>>>(attn);

    // 5) O = V @ P^T  [512x4096] (tf32-rounded)
    dim3 gAV(NPIX / TBN, CCH / TBM, BATCH);
    gemm_tc<0, 1, false, false, true><<<gAV, 256>>>(
        vb, attn, o, nullptr, nullptr, NPIX, NPIX, NPIX, NPIX,
        QKV_S, NN, CN, 0, 1.0f);

    // 6) out = x + Wo @ O + bo (full fp32 store)
    dim3 gProj(NPIX / TBN, CCH / TBM, BATCH);
    gemm_tc<0, 0, true, true, false><<<gProj, 256>>>(
        wr + 3LL * CCH * CCH, o, out, bo, x, CCH, CCH, NPIX, NPIX,
        0, CN, CN, CN, 1.0f);
}

// round 5
// speedup vs baseline: 5.9804x; 1.9748x over previous
#include <cuda_runtime.h>
#include <cuda_bf16.h>
#include <cstdint>

// B=2, C=512, N=4096. out = x + Wo@Attn(GN(x)) + bo, [B,C,H,W] fp32.
#define BATCH 2
#define CCH   512
#define NPIX  4096
#define NQKV  1536
#define GEPS  1e-6f

static const long long CN  = (long long)CCH * NPIX;    // 2M
static const long long NN  = (long long)NPIX * NPIX;   // 16M
static const long long QKVN = (long long)NPIX * NQKV;  // 6M

// scratch (device globals; bf16 operands, fp32 scores)
__device__ __nv_bfloat16 g_ht [BATCH * NPIX * CCH];          // hT  [B][pix][C]
__device__ __nv_bfloat16 g_qkv[(long long)BATCH * NPIX * NQKV]; // [B][pix][q|k|v]
__device__ float         g_attn[(long long)BATCH * NPIX * NPIX];
__device__ __nv_bfloat16 g_p  [(long long)BATCH * NPIX * NPIX]; // probs bf16
__device__ __nv_bfloat16 g_ot [BATCH * NPIX * CCH];          // OT [B][pix][C]
__device__ __nv_bfloat16 g_wqkv[NQKV * CCH];                 // concat(wq*s, wk, wv)
__device__ __nv_bfloat16 g_wo [CCH * CCH];
__device__ float         g_bqkv[NQKV];                       // concat(bq*s, bk, bv)
__device__ float         g_stat[BATCH * 32 * 2];

// ---------------------------------------------------------------------------
// PTX helpers
// ---------------------------------------------------------------------------
__device__ __forceinline__ void cpasync16(uint32_t s, const void* g) {
    asm volatile("cp.async.cg.shared.global [%0], [%1], 16;" :: "r"(s), "l"(g));
}
__device__ __forceinline__ uint32_t smem_u32(const void* p) {
    return (uint32_t)__cvta_generic_to_shared(p);
}
__device__ __forceinline__ void ldsm4(uint32_t r[4], uint32_t addr) {
    asm volatile("ldmatrix.sync.aligned.m8n8.x4.shared.b16 {%0,%1,%2,%3}, [%4];"
        : "=r"(r[0]), "=r"(r[1]), "=r"(r[2]), "=r"(r[3]) : "r"(addr));
}
__device__ __forceinline__ void ldsm4t(uint32_t r[4], uint32_t addr) {
    asm volatile("ldmatrix.sync.aligned.m8n8.x4.trans.shared.b16 {%0,%1,%2,%3}, [%4];"
        : "=r"(r[0]), "=r"(r[1]), "=r"(r[2]), "=r"(r[3]) : "r"(addr));
}
__device__ __forceinline__ void mma_bf16(float c[4], const uint32_t a[4],
                                         const uint32_t b[2]) {
    asm volatile(
        "mma.sync.aligned.m16n8k16.row.col.f32.bf16.bf16.f32 "
        "{%0,%1,%2,%3},{%4,%5,%6,%7},{%8,%9},{%0,%1,%2,%3};"
        : "+f"(c[0]), "+f"(c[1]), "+f"(c[2]), "+f"(c[3])
        : "r"(a[0]), "r"(a[1]), "r"(a[2]), "r"(a[3]), "r"(b[0]), "r"(b[1]));
}

// ---------------------------------------------------------------------------
// bf16 tensor-core GEMM: D[M][N] = A[M][K] * B^T (+bias) (+res)
//   A: bf16 [M][K] row-major.
//   TRB=0: B bf16 [N][K] (K-major rows). TRB=1: B bf16 [K][N] (n-major rows).
// Block tile 128x128x64(bf16), 256 thr = 8 warps (2x4), warp tile 64x32.
// m16n8k16 via ldmatrix; cp.async double-buffered; padded-stride smem
// (row strides 144/272 bytes -> LDSM banks 4r mod 32, conflict-free).
// BIAS_MODE: 0 none, 1 bias[m], 2 bias[n]. OUTBF: bf16 out else fp32.
// ---------------------------------------------------------------------------
#define BM 128
#define BN 128
#define BK 64
#define ASTR 144
#define BSTR_N 144
#define BSTR_T 272
#define ASTAGE (BM * ASTR)        // 18432
#define BSTAGE_N (BN * BSTR_N)    // 18432
#define BSTAGE_T (BK * BSTR_T)    // 17408
#define SMEM_NT (2 * (ASTAGE + BSTAGE_N))   // 73728
#define SMEM_TR (2 * (ASTAGE + BSTAGE_T))   // 71680

template<int BIAS_MODE, bool RES, bool TRB, bool OUTBF>
__global__ __launch_bounds__(256, 2) void gemm_bf16_tc(
    const __nv_bfloat16* __restrict__ A, const __nv_bfloat16* __restrict__ B,
    void* __restrict__ Cv,
    const float* __restrict__ bias, const float* __restrict__ res,
    int K, int lda, int ldb, int ldc,
    long long sA, long long sB, long long sC, long long sR)
{
    extern __shared__ char smem[];
    constexpr int BSTAGE = TRB ? BSTAGE_T : BSTAGE_N;
    const uint32_t sbA = smem_u32(smem);
    const uint32_t sbB = sbA + 2 * ASTAGE;

    const int tid  = threadIdx.x;
    const int wid  = tid >> 5;
    const int lane = tid & 31;
    const int g    = lane >> 2;
    const int tig  = lane & 3;
    const int sub  = lane >> 3;      // ldmatrix subtile id
    const int r8   = lane & 7;       // row within subtile
    const int m_w  = (wid >> 2) * 64;
    const int n_w  = (wid & 3) * 32;
    const int m0   = blockIdx.y * BM;
    const int n0   = blockIdx.x * BN;
    const int z    = blockIdx.z;

    const __nv_bfloat16* Ab = A + (long long)z * sA + (long long)m0 * lda;
    const __nv_bfloat16* Bb = TRB ? (B + (long long)z * sB + n0)
                                  : (B + (long long)z * sB + (long long)n0 * ldb);

    float acc[4][4][4];
    #pragma unroll
    for (int i = 0; i < 4; i++)
        #pragma unroll
        for (int j = 0; j < 4; j++)
            #pragma unroll
            for (int r = 0; r < 4; r++) acc[i][j][r] = 0.f;

    const int nk = K / BK;

    auto load = [&](int ks, int buf) {
        const uint32_t ab = sbA + buf * ASTAGE;
        const uint32_t bb = sbB + buf * BSTAGE;
        #pragma unroll
        for (int it = 0; it < 4; it++) {           // A: 1024 x 16B chunks
            int s = tid + it * 256;
            int r = s >> 3, c = s & 7;
            cpasync16(ab + r * ASTR + c * 16,
                      Ab + (long long)r * lda + ks * BK + c * 8);
        }
        if (!TRB) {
            #pragma unroll
            for (int it = 0; it < 4; it++) {       // B: 128 n-rows x 8 chunks
                int s = tid + it * 256;
                int r = s >> 3, c = s & 7;
                cpasync16(bb + r * BSTR_N + c * 16,
                          Bb + (long long)r * ldb + ks * BK + c * 8);
            }
        } else {
            #pragma unroll
            for (int it = 0; it < 4; it++) {       // B: 64 k-rows x 16 chunks
                int s = tid + it * 256;
                int r = s >> 4, c = s & 15;
                cpasync16(bb + r * BSTR_T + c * 16,
                          Bb + (long long)(ks * BK + r) * ldb + c * 8);
            }
        }
        asm volatile("cp.async.commit_group;");
    };

    load(0, 0);
    if (nk > 1) load(1, 1);

    #pragma unroll 1
    for (int ks = 0; ks < nk; ks++) {
        const int buf = ks & 1;
        if (ks + 1 < nk) asm volatile("cp.async.wait_group 1;");
        else             asm volatile("cp.async.wait_group 0;");
        __syncthreads();

        const uint32_t ab = sbA + buf * ASTAGE;
        const uint32_t bb = sbB + buf * BSTAGE;

        #pragma unroll
        for (int kk = 0; kk < 4; kk++) {           // four k16 steps in BK=64
            uint32_t af[4][4];
            #pragma unroll
            for (int i = 0; i < 4; i++) {
                uint32_t addr = ab + (m_w + 16 * i + (sub & 1) * 8 + r8) * ASTR
                              + kk * 32 + (sub >> 1) * 16;
                ldsm4(af[i], addr);
            }
            uint32_t bf[4][2];
            #pragma unroll
            for (int jj = 0; jj < 2; jj++) {
                uint32_t t[4];
                if (!TRB) {
                    uint32_t addr = bb + (n_w + 16 * jj + (sub >> 1) * 8 + r8) * BSTR_N
                                  + kk * 32 + (sub & 1) * 16;
                    ldsm4(t, addr);
                } else {
                    uint32_t addr = bb + (kk * 16 + (sub & 1) * 8 + r8) * BSTR_T
                                  + (n_w + 16 * jj + (sub >> 1) * 8) * 2;
                    ldsm4t(t, addr);
                }
                bf[2 * jj][0] = t[0]; bf[2 * jj][1] = t[1];
                bf[2 * jj + 1][0] = t[2]; bf[2 * jj + 1][1] = t[3];
            }
            #pragma unroll
            for (int i = 0; i < 4; i++)
                #pragma unroll
                for (int j = 0; j < 4; j++)
                    mma_bf16(acc[i][j], af[i], bf[j]);
        }
        __syncthreads();
        if (ks + 2 < nk) load(ks + 2, buf);
    }

    // epilogue: c0,c1 -> (row g, cols 2tig..+1); c2,c3 -> row g+8
    if (OUTBF) {
        __nv_bfloat16* C = (__nv_bfloat16*)Cv + (long long)z * sC;
        #pragma unroll
        for (int i = 0; i < 4; i++) {
            int r0 = m0 + m_w + 16 * i + g;
            int r1 = r0 + 8;
            float bm0 = (BIAS_MODE == 1) ? bias[r0] : 0.f;
            float bm1 = (BIAS_MODE == 1) ? bias[r1] : 0.f;
            #pragma unroll
            for (int j = 0; j < 4; j++) {
                int col = n0 + n_w + 8 * j + 2 * tig;
                float bn0 = 0.f, bn1 = 0.f;
                if (BIAS_MODE == 2) { bn0 = bias[col]; bn1 = bias[col + 1]; }
                float2 v0 = make_float2(acc[i][j][0] + bm0 + bn0,
                                        acc[i][j][1] + bm0 + bn1);
                float2 v1 = make_float2(acc[i][j][2] + bm1 + bn0,
                                        acc[i][j][3] + bm1 + bn1);
                *(__nv_bfloat162*)&C[(long long)r0 * ldc + col] = __float22bfloat162_rn(v0);
                *(__nv_bfloat162*)&C[(long long)r1 * ldc + col] = __float22bfloat162_rn(v1);
            }
        }
    } else {
        float* C = (float*)Cv + (long long)z * sC;
        const float* Rb = RES ? res + (long long)z * sR : nullptr;
        #pragma unroll
        for (int i = 0; i < 4; i++) {
            int r0 = m0 + m_w + 16 * i + g;
            int r1 = r0 + 8;
            float bm0 = (BIAS_MODE == 1) ? bias[r0] : 0.f;
            float bm1 = (BIAS_MODE == 1) ? bias[r1] : 0.f;
            #pragma unroll
            for (int j = 0; j < 4; j++) {
                int col = n0 + n_w + 8 * j + 2 * tig;
                long long o0 = (long long)r0 * ldc + col;
                long long o1 = (long long)r1 * ldc + col;
                float2 v0 = make_float2(acc[i][j][0] + bm0, acc[i][j][1] + bm0);
                float2 v1 = make_float2(acc[i][j][2] + bm1, acc[i][j][3] + bm1);
                if (RES) {
                    float2 a0 = *(const float2*)&Rb[o0];
                    float2 a1 = *(const float2*)&Rb[o1];
                    v0.x += a0.x; v0.y += a0.y;
                    v1.x += a1.x; v1.y += a1.y;
                }
                *(float2*)&C[o0] = v0;
                *(float2*)&C[o1] = v1;
            }
        }
    }
}

// ---------------------------------------------------------------------------
// Weight/bias prep: concat(wq*s, wk, wv) -> bf16; wo -> bf16; bias concat.
// ---------------------------------------------------------------------------
__global__ __launch_bounds__(256) void prep_weights(
    const float* __restrict__ wq, const float* __restrict__ wk,
    const float* __restrict__ wv, const float* __restrict__ wo,
    const float* __restrict__ bq, const float* __restrict__ bk,
    const float* __restrict__ bv,
    __nv_bfloat16* __restrict__ wqkv, __nv_bfloat16* __restrict__ wob,
    float* __restrict__ bqkv)
{
    const float scale = 0.044194173824159216f;   // 512^-0.5
    int idx = blockIdx.x * 256 + threadIdx.x;    // 0 .. 1048575
    if (idx < NQKV * CCH) {
        int row = idx >> 9, col = idx & 511;
        int which = row >> 9, rr = row & 511;
        float v = which == 0 ? wq[rr * 512 + col] * scale
                : which == 1 ? wk[rr * 512 + col]
                             : wv[rr * 512 + col];
        wqkv[idx] = __float2bfloat16_rn(v);
        if (idx < NQKV) {
            int w2 = idx >> 9, r2 = idx & 511;
            bqkv[idx] = w2 == 0 ? bq[r2] * scale : w2 == 1 ? bk[r2] : bv[r2];
        }
    } else {
        int j = idx - NQKV * CCH;
        wob[j] = __float2bfloat16_rn(wo[j]);
    }
}

// ---------------------------------------------------------------------------
// GroupNorm stats + apply-with-transpose (bf16 out)
// ---------------------------------------------------------------------------
__global__ __launch_bounds__(256) void gn_stats_kernel(
    const float* __restrict__ x, float* __restrict__ stat)
{
    const int bg = blockIdx.x;
    const long long base = (long long)bg * 65536;
    const int t = threadIdx.x;
    float s = 0.f, ss = 0.f;
    #pragma unroll 8
    for (int i = t; i < 65536; i += 256) {
        float v = x[base + i];
        s += v; ss += v * v;
    }
    #pragma unroll
    for (int off = 16; off; off >>= 1) {
        s  += __shfl_down_sync(0xffffffffu, s,  off);
        ss += __shfl_down_sync(0xffffffffu, ss, off);
    }
    __shared__ float shs[8], shss[8];
    int wid = t >> 5, lane = t & 31;
    if (lane == 0) { shs[wid] = s; shss[wid] = ss; }
    __syncthreads();
    if (t == 0) {
        float ts = 0.f, tss = 0.f;
        #pragma unroll
        for (int i = 0; i < 8; i++) { ts += shs[i]; tss += shss[i]; }
        float mean = ts * (1.f / 65536.f);
        float var  = tss * (1.f / 65536.f) - mean * mean;
        stat[2 * bg]     = mean;
        stat[2 * bg + 1] = rsqrtf(var + GEPS);
    }
}

__global__ __launch_bounds__(256) void gn_apply_t_kernel(
    const float* __restrict__ x, const float* __restrict__ w,
    const float* __restrict__ b, const float* __restrict__ stat,
    __nv_bfloat16* __restrict__ ht)
{
    __shared__ float tile[32][33];
    const int p0 = blockIdx.x * 32;
    const int c0 = blockIdx.y * 32;
    const int bb = blockIdx.z;
    const int tx = threadIdx.x, ty = threadIdx.y;   // (32, 8)
    const long long xb = (long long)bb * CN;

    #pragma unroll
    for (int r = 0; r < 4; r++) {
        int cl = ty + 8 * r;
        tile[cl][tx] = x[xb + (long long)(c0 + cl) * NPIX + p0 + tx];
    }
    __syncthreads();
    const int c = c0 + tx;
    const int gidx = c >> 4;
    const float mean = stat[2 * (bb * 32 + gidx)];
    const float rstd = stat[2 * (bb * 32 + gidx) + 1];
    const float sc = rstd * w[c];
    const float sh = b[c] - mean * sc;
    #pragma unroll
    for (int r = 0; r < 4; r++) {
        int pl = ty + 8 * r;
        float v = tile[tx][pl] * sc + sh;
        ht[xb + (long long)(p0 + pl) * CCH + c] = __float2bfloat16_rn(v);
    }
}

// ---------------------------------------------------------------------------
// Row softmax: fp32 scores in, bf16 probs out
// ---------------------------------------------------------------------------
__global__ __launch_bounds__(256) void softmax_kernel(
    const float* __restrict__ attn, __nv_bfloat16* __restrict__ p)
{
    const float* s = attn + (long long)blockIdx.x * NPIX;
    __nv_bfloat16* po = p + (long long)blockIdx.x * NPIX;
    const int t = threadIdx.x;
    float v[16];
    float mx = -1e30f;
    #pragma unroll
    for (int i = 0; i < 16; i++) {
        v[i] = s[t + i * 256];
        mx = fmaxf(mx, v[i]);
    }
    #pragma unroll
    for (int off = 16; off; off >>= 1)
        mx = fmaxf(mx, __shfl_xor_sync(0xffffffffu, mx, off));
    __shared__ float sh[8];
    __shared__ float blk[2];
    int wid = t >> 5, lane = t & 31;
    if (lane == 0) sh[wid] = mx;
    __syncthreads();
    if (t == 0) {
        float m = sh[0];
        #pragma unroll
        for (int i = 1; i < 8; i++) m = fmaxf(m, sh[i]);
        blk[0] = m;
    }
    __syncthreads();
    mx = blk[0];
    float sum = 0.f;
    #pragma unroll
    for (int i = 0; i < 16; i++) {
        v[i] = __expf(v[i] - mx);
        sum += v[i];
    }
    #pragma unroll
    for (int off = 16; off; off >>= 1)
        sum += __shfl_xor_sync(0xffffffffu, sum, off);
    if (lane == 0) sh[wid] = sum;
    __syncthreads();
    if (t == 0) {
        float tot = 0.f;
        #pragma unroll
        for (int i = 0; i < 8; i++) tot += sh[i];
        blk[1] = 1.f / tot;
    }
    __syncthreads();
    const float inv = blk[1];
    #pragma unroll
    for (int i = 0; i < 16; i++)
        po[t + i * 256] = __float2bfloat16_rn(v[i] * inv);
}

// ---------------------------------------------------------------------------
extern "C" void kernel_launch(void* const* d_in, const int* in_sizes, int n_in,
                              void* d_out, int out_size)
{
    const float* x    = (const float*)d_in[0];
    const float* gn_w = (const float*)d_in[1];
    const float* gn_b = (const float*)d_in[2];
    const float* wq   = (const float*)d_in[3];
    const float* bq   = (const float*)d_in[4];
    const float* wk   = (const float*)d_in[5];
    const float* bk   = (const float*)d_in[6];
    const float* wv   = (const float*)d_in[7];
    const float* bv   = (const float*)d_in[8];
    const float* wo   = (const float*)d_in[9];
    const float* bo   = (const float*)d_in[10];
    float* out = (float*)d_out;

    __nv_bfloat16 *ht, *qkv, *p, *ot, *wqkv, *wob;
    float *attn, *bqkv, *stat;
    cudaGetSymbolAddress((void**)&ht,   g_ht);
    cudaGetSymbolAddress((void**)&qkv,  g_qkv);
    cudaGetSymbolAddress((void**)&attn, g_attn);
    cudaGetSymbolAddress((void**)&p,    g_p);
    cudaGetSymbolAddress((void**)&ot,   g_ot);
    cudaGetSymbolAddress((void**)&wqkv, g_wqkv);
    cudaGetSymbolAddress((void**)&wob,  g_wo);
    cudaGetSymbolAddress((void**)&bqkv, g_bqkv);
    cudaGetSymbolAddress((void**)&stat, g_stat);

    // raise dynamic smem limits (host-side, idempotent)
    cudaFuncSetAttribute(gemm_bf16_tc<2, false, false, true >,
        cudaFuncAttributeMaxDynamicSharedMemorySize, SMEM_NT);
    cudaFuncSetAttribute(gemm_bf16_tc<0, false, false, false>,
        cudaFuncAttributeMaxDynamicSharedMemorySize, SMEM_NT);
    cudaFuncSetAttribute(gemm_bf16_tc<0, false, true , true >,
        cudaFuncAttributeMaxDynamicSharedMemorySize, SMEM_TR);
    cudaFuncSetAttribute(gemm_bf16_tc<1, true , false, false>,
        cudaFuncAttributeMaxDynamicSharedMemorySize, SMEM_NT);

    // 0) weights -> bf16 (scale folded into wq/bq)
    prep_weights<<<(NQKV * CCH + CCH * CCH) / 256, 256>>>(
        wq, wk, wv, wo, bq, bk, bv, wqkv, wob, bqkv);

    // 1) GroupNorm -> hT bf16 [B][pix][C]
    gn_stats_kernel<<<BATCH * 32, 256>>>(x, stat);
    gn_apply_t_kernel<<<dim3(NPIX / 32, CCH / 32, BATCH), dim3(32, 8)>>>(
        x, gn_w, gn_b, stat, ht);

    // 2) fused QKV: qkvT[pix][1536] = hT @ wqkv^T + bqkv[n]
    dim3 gQKV(NQKV / BN, NPIX / BM, BATCH);      // (12, 32, 2)
    gemm_bf16_tc<2, false, false, true><<<gQKV, 256, SMEM_NT>>>(
        ht, wqkv, qkv, bqkv, nullptr, CCH, CCH, CCH, NQKV,
        CN, 0, QKVN, 0);

    // 3) S = qT @ kT^T  (scale pre-folded), fp32 scores
    dim3 gS(NPIX / BN, NPIX / BM, BATCH);        // (32, 32, 2)
    gemm_bf16_tc<0, false, false, false><<<gS, 256, SMEM_NT>>>(
        qkv, qkv + 512, attn, nullptr, nullptr, CCH, NQKV, NQKV, NPIX,
        QKVN, QKVN, NN, 0);

    // 4) softmax -> bf16 probs
    softmax_kernel<<<BATCH * NPIX, 256>>>(attn, p);

    // 5) OT[pix][C] = P @ vT   (vT = qkv cols 1024..1535, trans-B)
    dim3 gAV(CCH / BN, NPIX / BM, BATCH);        // (4, 32, 2)
    gemm_bf16_tc<0, false, true, true><<<gAV, 256, SMEM_TR>>>(
        p, qkv + 1024, ot, nullptr, nullptr, NPIX, NPIX, NQKV, CCH,
        NN, QKVN, CN, 0);

    // 6) out = x + wo @ OT^T + bo[m]  (fp32)
    dim3 gF(NPIX / BN, CCH / BM, BATCH);         // (32, 4, 2)
    gemm_bf16_tc<1, true, false, false><<<gF, 256, SMEM_NT>>>(
        wob, ot, out, bo, x, CCH, CCH, CCH, NPIX,
        0, CN, CN, CN);
}

// round 6
// speedup vs baseline: 6.0344x; 1.0090x over previous
#include <cuda_runtime.h>
#include <cuda_bf16.h>
#include <cstdint>

// B=2, C=512, N=4096. out = x + Wo@Attn(GN(x)) + bo, [B,C,H,W] fp32.
#define BATCH 2
#define CCH   512
#define NPIX  4096
#define NQKV  1536
#define GEPS  1e-6f

static const long long CN  = (long long)CCH * NPIX;    // 2M
static const long long NN  = (long long)NPIX * NPIX;   // 16M
static const long long QKVN = (long long)NPIX * NQKV;  // 6M

// scratch (device globals; bf16 operands, fp32 scores)
__device__ __nv_bfloat16 g_ht [BATCH * NPIX * CCH];             // hT [B][pix][C]
__device__ __nv_bfloat16 g_qkv[(long long)BATCH * NPIX * NQKV]; // [B][pix][q|k|v]
__device__ float         g_attn[(long long)BATCH * NPIX * NPIX];
__device__ __nv_bfloat16 g_p  [(long long)BATCH * NPIX * NPIX]; // probs bf16
__device__ __nv_bfloat16 g_ot [BATCH * NPIX * CCH];             // OT [B][pix][C]
__device__ __nv_bfloat16 g_wqkv[NQKV * CCH];                    // concat(wq*s,wk,wv)
__device__ __nv_bfloat16 g_wo [CCH * CCH];
__device__ float         g_bqkv[NQKV];
__device__ float         g_stat[BATCH * 32 * 2];

// ---------------------------------------------------------------------------
// PTX helpers
// ---------------------------------------------------------------------------
__device__ __forceinline__ void cpasync16(uint32_t s, const void* g) {
    asm volatile("cp.async.cg.shared.global [%0], [%1], 16;" :: "r"(s), "l"(g));
}
__device__ __forceinline__ uint32_t smem_u32(const void* p) {
    return (uint32_t)__cvta_generic_to_shared(p);
}
__device__ __forceinline__ void ldsm4(uint32_t r[4], uint32_t addr) {
    asm volatile("ldmatrix.sync.aligned.m8n8.x4.shared.b16 {%0,%1,%2,%3}, [%4];"
        : "=r"(r[0]), "=r"(r[1]), "=r"(r[2]), "=r"(r[3]) : "r"(addr));
}
__device__ __forceinline__ void ldsm4t(uint32_t r[4], uint32_t addr) {
    asm volatile("ldmatrix.sync.aligned.m8n8.x4.trans.shared.b16 {%0,%1,%2,%3}, [%4];"
        : "=r"(r[0]), "=r"(r[1]), "=r"(r[2]), "=r"(r[3]) : "r"(addr));
}
__device__ __forceinline__ void mma_bf16(float c[4], const uint32_t a[4],
                                         const uint32_t b[2]) {
    asm volatile(
        "mma.sync.aligned.m16n8k16.row.col.f32.bf16.bf16.f32 "
        "{%0,%1,%2,%3},{%4,%5,%6,%7},{%8,%9},{%0,%1,%2,%3};"
        : "+f"(c[0]), "+f"(c[1]), "+f"(c[2]), "+f"(c[3])
        : "r"(a[0]), "r"(a[1]), "r"(a[2]), "r"(a[3]), "r"(b[0]), "r"(b[1]));
}

// ---------------------------------------------------------------------------
// bf16 tensor-core GEMM: D[M][N] = A[M][K] * B^T (+bias) (+res)
//   A: bf16 [M][K] row-major.
//   TRB=0: B bf16 [N][K]. TRB=1: B bf16 [K][N] (ldmatrix.trans).
// Block tile 128x128x64, 256 thr = 8 warps (2x4), warp tile 64x32, m16n8k16.
// 3-stage cp.async pipeline, ONE __syncthreads per chunk, wait_group 1.
// ---------------------------------------------------------------------------
#define BM 128
#define BN 128
#define BK 64
#define ASTR 144
#define BSTR_N 144
#define BSTR_T 272
#define ASTAGE (BM * ASTR)        // 18432
#define BSTAGE_N (BN * BSTR_N)    // 18432
#define BSTAGE_T (BK * BSTR_T)    // 17408
#define SMEM3_NT (3 * (ASTAGE + BSTAGE_N))   // 110592
#define SMEM3_TR (3 * (ASTAGE + BSTAGE_T))   // 107520

template<int BIAS_MODE, bool RES, bool TRB, bool OUTBF>
__global__ __launch_bounds__(256, 2) void gemm_bf16_tc(
    const __nv_bfloat16* __restrict__ A, const __nv_bfloat16* __restrict__ B,
    void* __restrict__ Cv,
    const float* __restrict__ bias, const float* __restrict__ res,
    int K, int lda, int ldb, int ldc,
    long long sA, long long sB, long long sC, long long sR)
{
    extern __shared__ char smem[];
    constexpr int BSTAGE = TRB ? BSTAGE_T : BSTAGE_N;
    const uint32_t sbA = smem_u32(smem);
    const uint32_t sbB = sbA + 3 * ASTAGE;

    const int tid  = threadIdx.x;
    const int wid  = tid >> 5;
    const int lane = tid & 31;
    const int g    = lane >> 2;
    const int tig  = lane & 3;
    const int sub  = lane >> 3;
    const int r8   = lane & 7;
    const int m_w  = (wid >> 2) * 64;
    const int n_w  = (wid & 3) * 32;
    const int m0   = blockIdx.y * BM;
    const int n0   = blockIdx.x * BN;
    const int z    = blockIdx.z;

    const __nv_bfloat16* Ab = A + (long long)z * sA + (long long)m0 * lda;
    const __nv_bfloat16* Bb = TRB ? (B + (long long)z * sB + n0)
                                  : (B + (long long)z * sB + (long long)n0 * ldb);

    float acc[4][4][4];
    #pragma unroll
    for (int i = 0; i < 4; i++)
        #pragma unroll
        for (int j = 0; j < 4; j++)
            #pragma unroll
            for (int r = 0; r < 4; r++) acc[i][j][r] = 0.f;

    const int nk = K / BK;

    auto load = [&](int ks, int buf) {
        const uint32_t ab = sbA + buf * ASTAGE;
        const uint32_t bb = sbB + buf * BSTAGE;
        #pragma unroll
        for (int it = 0; it < 4; it++) {           // A: 1024 x 16B chunks
            int s = tid + it * 256;
            int r = s >> 3, c = s & 7;
            cpasync16(ab + r * ASTR + c * 16,
                      Ab + (long long)r * lda + ks * BK + c * 8);
        }
        if (!TRB) {
            #pragma unroll
            for (int it = 0; it < 4; it++) {       // B: 128 n-rows x 8 chunks
                int s = tid + it * 256;
                int r = s >> 3, c = s & 7;
                cpasync16(bb + r * BSTR_N + c * 16,
                          Bb + (long long)r * ldb + ks * BK + c * 8);
            }
        } else {
            #pragma unroll
            for (int it = 0; it < 4; it++) {       // B: 64 k-rows x 16 chunks
                int s = tid + it * 256;
                int r = s >> 4, c = s & 15;
                cpasync16(bb + r * BSTR_T + c * 16,
                          Bb + (long long)(ks * BK + r) * ldb + c * 8);
            }
        }
        asm volatile("cp.async.commit_group;");
    };

    // prologue: two chunks in flight
    load(0, 0);
    if (nk > 1) load(1, 1);

    #pragma unroll 1
    for (int ks = 0; ks < nk; ks++) {
        const int buf = ks % 3;
        if (ks + 1 < nk) asm volatile("cp.async.wait_group 1;");
        else             asm volatile("cp.async.wait_group 0;");
        __syncthreads();                       // single barrier per chunk
        if (ks + 2 < nk) load(ks + 2, (ks + 2) % 3);   // writes slot (ks-1)%3

        const uint32_t ab = sbA + buf * ASTAGE;
        const uint32_t bb = sbB + buf * BSTAGE;

        #pragma unroll
        for (int kk = 0; kk < 4; kk++) {
            uint32_t af[4][4];
            #pragma unroll
            for (int i = 0; i < 4; i++) {
                uint32_t addr = ab + (m_w + 16 * i + (sub & 1) * 8 + r8) * ASTR
                              + kk * 32 + (sub >> 1) * 16;
                ldsm4(af[i], addr);
            }
            uint32_t bf[4][2];
            #pragma unroll
            for (int jj = 0; jj < 2; jj++) {
                uint32_t t[4];
                if (!TRB) {
                    uint32_t addr = bb + (n_w + 16 * jj + (sub >> 1) * 8 + r8) * BSTR_N
                                  + kk * 32 + (sub & 1) * 16;
                    ldsm4(t, addr);
                } else {
                    uint32_t addr = bb + (kk * 16 + (sub & 1) * 8 + r8) * BSTR_T
                                  + (n_w + 16 * jj + (sub >> 1) * 8) * 2;
                    ldsm4t(t, addr);
                }
                bf[2 * jj][0] = t[0]; bf[2 * jj][1] = t[1];
                bf[2 * jj + 1][0] = t[2]; bf[2 * jj + 1][1] = t[3];
            }
            #pragma unroll
            for (int i = 0; i < 4; i++)
                #pragma unroll
                for (int j = 0; j < 4; j++)
                    mma_bf16(acc[i][j], af[i], bf[j]);
        }
    }

    // epilogue
    if (OUTBF) {
        __nv_bfloat16* C = (__nv_bfloat16*)Cv + (long long)z * sC;
        #pragma unroll
        for (int i = 0; i < 4; i++) {
            int r0 = m0 + m_w + 16 * i + g;
            int r1 = r0 + 8;
            float bm0 = (BIAS_MODE == 1) ? bias[r0] : 0.f;
            float bm1 = (BIAS_MODE == 1) ? bias[r1] : 0.f;
            #pragma unroll
            for (int j = 0; j < 4; j++) {
                int col = n0 + n_w + 8 * j + 2 * tig;
                float bn0 = 0.f, bn1 = 0.f;
                if (BIAS_MODE == 2) { bn0 = bias[col]; bn1 = bias[col + 1]; }
                float2 v0 = make_float2(acc[i][j][0] + bm0 + bn0,
                                        acc[i][j][1] + bm0 + bn1);
                float2 v1 = make_float2(acc[i][j][2] + bm1 + bn0,
                                        acc[i][j][3] + bm1 + bn1);
                *(__nv_bfloat162*)&C[(long long)r0 * ldc + col] = __float22bfloat162_rn(v0);
                *(__nv_bfloat162*)&C[(long long)r1 * ldc + col] = __float22bfloat162_rn(v1);
            }
        }
    } else {
        float* C = (float*)Cv + (long long)z * sC;
        const float* Rb = RES ? res + (long long)z * sR : nullptr;
        #pragma unroll
        for (int i = 0; i < 4; i++) {
            int r0 = m0 + m_w + 16 * i + g;
            int r1 = r0 + 8;
            float bm0 = (BIAS_MODE == 1) ? bias[r0] : 0.f;
            float bm1 = (BIAS_MODE == 1) ? bias[r1] : 0.f;
            #pragma unroll
            for (int j = 0; j < 4; j++) {
                int col = n0 + n_w + 8 * j + 2 * tig;
                long long o0 = (long long)r0 * ldc + col;
                long long o1 = (long long)r1 * ldc + col;
                float2 v0 = make_float2(acc[i][j][0] + bm0, acc[i][j][1] + bm0);
                float2 v1 = make_float2(acc[i][j][2] + bm1, acc[i][j][3] + bm1);
                if (RES) {
                    float2 a0 = *(const float2*)&Rb[o0];
                    float2 a1 = *(const float2*)&Rb[o1];
                    v0.x += a0.x; v0.y += a0.y;
                    v1.x += a1.x; v1.y += a1.y;
                }
                *(float2*)&C[o0] = v0;
                *(float2*)&C[o1] = v1;
            }
        }
    }
}

// ---------------------------------------------------------------------------
// Weight/bias prep: concat(wq*s, wk, wv) -> bf16; wo -> bf16; bias concat.
// ---------------------------------------------------------------------------
__global__ __launch_bounds__(256) void prep_weights(
    const float* __restrict__ wq, const float* __restrict__ wk,
    const float* __restrict__ wv, const float* __restrict__ wo,
    const float* __restrict__ bq, const float* __restrict__ bk,
    const float* __restrict__ bv,
    __nv_bfloat16* __restrict__ wqkv, __nv_bfloat16* __restrict__ wob,
    float* __restrict__ bqkv)
{
    const float scale = 0.044194173824159216f;   // 512^-0.5
    int idx = blockIdx.x * 256 + threadIdx.x;
    if (idx < NQKV * CCH) {
        int row = idx >> 9, col = idx & 511;
        int which = row >> 9, rr = row & 511;
        float v = which == 0 ? wq[rr * 512 + col] * scale
                : which == 1 ? wk[rr * 512 + col]
                             : wv[rr * 512 + col];
        wqkv[idx] = __float2bfloat16_rn(v);
        if (idx < NQKV) {
            int w2 = idx >> 9, r2 = idx & 511;
            bqkv[idx] = w2 == 0 ? bq[r2] * scale : w2 == 1 ? bk[r2] : bv[r2];
        }
    } else {
        int j = idx - NQKV * CCH;
        wob[j] = __float2bfloat16_rn(wo[j]);
    }
}

// ---------------------------------------------------------------------------
// GroupNorm stats + apply-with-transpose (bf16 out)
// ---------------------------------------------------------------------------
__global__ __launch_bounds__(256) void gn_stats_kernel(
    const float* __restrict__ x, float* __restrict__ stat)
{
    const int bg = blockIdx.x;
    const long long base = (long long)bg * 65536;
    const int t = threadIdx.x;
    float s = 0.f, ss = 0.f;
    #pragma unroll 8
    for (int i = t; i < 65536; i += 256) {
        float v = x[base + i];
        s += v; ss += v * v;
    }
    #pragma unroll
    for (int off = 16; off; off >>= 1) {
        s  += __shfl_down_sync(0xffffffffu, s,  off);
        ss += __shfl_down_sync(0xffffffffu, ss, off);
    }
    __shared__ float shs[8], shss[8];
    int wid = t >> 5, lane = t & 31;
    if (lane == 0) { shs[wid] = s; shss[wid] = ss; }
    __syncthreads();
    if (t == 0) {
        float ts = 0.f, tss = 0.f;
        #pragma unroll
        for (int i = 0; i < 8; i++) { ts += shs[i]; tss += shss[i]; }
        float mean = ts * (1.f / 65536.f);
        float var  = tss * (1.f / 65536.f) - mean * mean;
        stat[2 * bg]     = mean;
        stat[2 * bg + 1] = rsqrtf(var + GEPS);
    }
}

__global__ __launch_bounds__(256) void gn_apply_t_kernel(
    const float* __restrict__ x, const float* __restrict__ w,
    const float* __restrict__ b, const float* __restrict__ stat,
    __nv_bfloat16* __restrict__ ht)
{
    __shared__ float tile[32][33];
    const int p0 = blockIdx.x * 32;
    const int c0 = blockIdx.y * 32;
    const int bb = blockIdx.z;
    const int tx = threadIdx.x, ty = threadIdx.y;   // (32, 8)
    const long long xb = (long long)bb * CN;

    #pragma unroll
    for (int r = 0; r < 4; r++) {
        int cl = ty + 8 * r;
        tile[cl][tx] = x[xb + (long long)(c0 + cl) * NPIX + p0 + tx];
    }
    __syncthreads();
    const int c = c0 + tx;
    const int gidx = c >> 4;
    const float mean = stat[2 * (bb * 32 + gidx)];
    const float rstd = stat[2 * (bb * 32 + gidx) + 1];
    const float sc = rstd * w[c];
    const float sh = b[c] - mean * sc;
    #pragma unroll
    for (int r = 0; r < 4; r++) {
        int pl = ty + 8 * r;
        float v = tile[tx][pl] * sc + sh;
        ht[xb + (long long)(p0 + pl) * CCH + c] = __float2bfloat16_rn(v);
    }
}

// ---------------------------------------------------------------------------
// Row softmax: fp32 scores in, bf16 probs out (vectorized)
// ---------------------------------------------------------------------------
__global__ __launch_bounds__(256) void softmax_kernel(
    const float* __restrict__ attn, __nv_bfloat16* __restrict__ p)
{
    const float4* s = (const float4*)(attn + (long long)blockIdx.x * NPIX);
    __nv_bfloat162* po = (__nv_bfloat162*)(p + (long long)blockIdx.x * NPIX);
    const int t = threadIdx.x;
    float4 v[4];
    float mx = -1e30f;
    #pragma unroll
    for (int i = 0; i < 4; i++) {
        v[i] = s[t + i * 256];
        mx = fmaxf(mx, fmaxf(fmaxf(v[i].x, v[i].y), fmaxf(v[i].z, v[i].w)));
    }
    #pragma unroll
    for (int off = 16; off; off >>= 1)
        mx = fmaxf(mx, __shfl_xor_sync(0xffffffffu, mx, off));
    __shared__ float sh[8];
    __shared__ float blk[2];
    int wid = t >> 5, lane = t & 31;
    if (lane == 0) sh[wid] = mx;
    __syncthreads();
    if (t == 0) {
        float m = sh[0];
        #pragma unroll
        for (int i = 1; i < 8; i++) m = fmaxf(m, sh[i]);
        blk[0] = m;
    }
    __syncthreads();
    mx = blk[0];
    float sum = 0.f;
    #pragma unroll
    for (int i = 0; i < 4; i++) {
        v[i].x = __expf(v[i].x - mx); v[i].y = __expf(v[i].y - mx);
        v[i].z = __expf(v[i].z - mx); v[i].w = __expf(v[i].w - mx);
        sum += (v[i].x + v[i].y) + (v[i].z + v[i].w);
    }
    #pragma unroll
    for (int off = 16; off; off >>= 1)
        sum += __shfl_xor_sync(0xffffffffu, sum, off);
    if (lane == 0) sh[wid] = sum;
    __syncthreads();
    if (t == 0) {
        float tot = 0.f;
        #pragma unroll
        for (int i = 0; i < 8; i++) tot += sh[i];
        blk[1] = 1.f / tot;
    }
    __syncthreads();
    const float inv = blk[1];
    #pragma unroll
    for (int i = 0; i < 4; i++) {
        po[2 * (t + i * 256)] =
            __float22bfloat162_rn(make_float2(v[i].x * inv, v[i].y * inv));
        po[2 * (t + i * 256) + 1] =
            __float22bfloat162_rn(make_float2(v[i].z * inv, v[i].w * inv));
    }
}

// ---------------------------------------------------------------------------
extern "C" void kernel_launch(void* const* d_in, const int* in_sizes, int n_in,
                              void* d_out, int out_size)
{
    const float* x    = (const float*)d_in[0];
    const float* gn_w = (const float*)d_in[1];
    const float* gn_b = (const float*)d_in[2];
    const float* wq   = (const float*)d_in[3];
    const float* bq   = (const float*)d_in[4];
    const float* wk   = (const float*)d_in[5];
    const float* bk   = (const float*)d_in[6];
    const float* wv   = (const float*)d_in[7];
    const float* bv   = (const float*)d_in[8];
    const float* wo   = (const float*)d_in[9];
    const float* bo   = (const float*)d_in[10];
    float* out = (float*)d_out;

    __nv_bfloat16 *ht, *qkv, *p, *ot, *wqkv, *wob;
    float *attn, *bqkv, *stat;
    cudaGetSymbolAddress((void**)&ht,   g_ht);
    cudaGetSymbolAddress((void**)&qkv,  g_qkv);
    cudaGetSymbolAddress((void**)&attn, g_attn);
    cudaGetSymbolAddress((void**)&p,    g_p);
    cudaGetSymbolAddress((void**)&ot,   g_ot);
    cudaGetSymbolAddress((void**)&wqkv, g_wqkv);
    cudaGetSymbolAddress((void**)&wob,  g_wo);
    cudaGetSymbolAddress((void**)&bqkv, g_bqkv);
    cudaGetSymbolAddress((void**)&stat, g_stat);

    cudaFuncSetAttribute(gemm_bf16_tc<2, false, false, true >,
        cudaFuncAttributeMaxDynamicSharedMemorySize, SMEM3_NT);
    cudaFuncSetAttribute(gemm_bf16_tc<0, false, false, false>,
        cudaFuncAttributeMaxDynamicSharedMemorySize, SMEM3_NT);
    cudaFuncSetAttribute(gemm_bf16_tc<0, false, true , true >,
        cudaFuncAttributeMaxDynamicSharedMemorySize, SMEM3_TR);
    cudaFuncSetAttribute(gemm_bf16_tc<1, true , false, false>,
        cudaFuncAttributeMaxDynamicSharedMemorySize, SMEM3_NT);

    // 0) weights -> bf16 (scale folded into wq/bq)
    prep_weights<<<(NQKV * CCH + CCH * CCH) / 256, 256>>>(
        wq, wk, wv, wo, bq, bk, bv, wqkv, wob, bqkv);

    // 1) GroupNorm -> hT bf16 [B][pix][C]
    gn_stats_kernel<<<BATCH * 32, 256>>>(x, stat);
    gn_apply_t_kernel<<<dim3(NPIX / 32, CCH / 32, BATCH), dim3(32, 8)>>>(
        x, gn_w, gn_b, stat, ht);

    // 2) fused QKV: qkvT[pix][1536] = hT @ wqkv^T + bqkv[n]
    dim3 gQKV(NQKV / BN, NPIX / BM, BATCH);
    gemm_bf16_tc<2, false, false, true><<<gQKV, 256, SMEM3_NT>>>(
        ht, wqkv, qkv, bqkv, nullptr, CCH, CCH, CCH, NQKV,
        CN, 0, QKVN, 0);

    // 3) S = qT @ kT^T (scale pre-folded), fp32 scores
    dim3 gS(NPIX / BN, NPIX / BM, BATCH);
    gemm_bf16_tc<0, false, false, false><<<gS, 256, SMEM3_NT>>>(
        qkv, qkv + 512, attn, nullptr, nullptr, CCH, NQKV, NQKV, NPIX,
        QKVN, QKVN, NN, 0);

    // 4) softmax -> bf16 probs
    softmax_kernel<<<BATCH * NPIX, 256>>>(attn, p);

    // 5) OT[pix][C] = P @ vT (vT = qkv cols 1024..1535, trans-B)
    dim3 gAV(CCH / BN, NPIX / BM, BATCH);
    gemm_bf16_tc<0, false, true, true><<<gAV, 256, SMEM3_TR>>>(
        p, qkv + 1024, ot, nullptr, nullptr, NPIX, NPIX, NQKV, CCH,
        NN, QKVN, CN, 0);

    // 6) out = x + wo @ OT^T + bo[m] (fp32)
    dim3 gF(NPIX / BN, CCH / BM, BATCH);
    gemm_bf16_tc<1, true, false, false><<<gF, 256, SMEM3_NT>>>(
        wob, ot, out, bo, x, CCH, CCH, CCH, NPIX,
        0, CN, CN, CN);
}

// round 7
// speedup vs baseline: 6.0388x; 1.0007x over previous
#include <cuda_runtime.h>
#include <cuda_bf16.h>
#include <cstdint>

// B=2, C=512, N=4096. out = x + Wo@Attn(GN(x)) + bo, [B,C,H,W] fp32.
#define BATCH 2
#define CCH   512
#define NPIX  4096
#define NQKV  1536
#define GEPS  1e-6f

static const long long CN  = (long long)CCH * NPIX;    // 2M
static const long long NN  = (long long)NPIX * NPIX;   // 16M
static const long long QKVN = (long long)NPIX * NQKV;  // 6M

// scratch (device globals; bf16 operands, fp32 scores)
__device__ __nv_bfloat16 g_ht [BATCH * NPIX * CCH];             // hT [B][pix][C]
__device__ __nv_bfloat16 g_qkv[(long long)BATCH * NPIX * NQKV]; // [B][pix][q|k|v]
__device__ float         g_attn[(long long)BATCH * NPIX * NPIX];
__device__ __nv_bfloat16 g_p  [(long long)BATCH * NPIX * NPIX]; // probs bf16
__device__ __nv_bfloat16 g_ot [BATCH * NPIX * CCH];             // OT [B][pix][C]
__device__ __nv_bfloat16 g_wqkv[NQKV * CCH];                    // concat(wq*s,wk,wv)
__device__ __nv_bfloat16 g_wo [CCH * CCH];
__device__ float         g_bqkv[NQKV];
__device__ float         g_stat[BATCH * 32 * 2];

// ---------------------------------------------------------------------------
// PTX helpers
// ---------------------------------------------------------------------------
__device__ __forceinline__ void cpasync16(uint32_t s, const void* g) {
    asm volatile("cp.async.cg.shared.global [%0], [%1], 16;" :: "r"(s), "l"(g));
}
__device__ __forceinline__ uint32_t smem_u32(const void* p) {
    return (uint32_t)__cvta_generic_to_shared(p);
}
__device__ __forceinline__ void ldsm4(uint32_t r[4], uint32_t addr) {
    asm volatile("ldmatrix.sync.aligned.m8n8.x4.shared.b16 {%0,%1,%2,%3}, [%4];"
        : "=r"(r[0]), "=r"(r[1]), "=r"(r[2]), "=r"(r[3]) : "r"(addr));
}
__device__ __forceinline__ void ldsm4t(uint32_t r[4], uint32_t addr) {
    asm volatile("ldmatrix.sync.aligned.m8n8.x4.trans.shared.b16 {%0,%1,%2,%3}, [%4];"
        : "=r"(r[0]), "=r"(r[1]), "=r"(r[2]), "=r"(r[3]) : "r"(addr));
}
__device__ __forceinline__ void mma_bf16(float c[4], const uint32_t a[4],
                                         const uint32_t b0, const uint32_t b1) {
    asm volatile(
        "mma.sync.aligned.m16n8k16.row.col.f32.bf16.bf16.f32 "
        "{%0,%1,%2,%3},{%4,%5,%6,%7},{%8,%9},{%0,%1,%2,%3};"
        : "+f"(c[0]), "+f"(c[1]), "+f"(c[2]), "+f"(c[3])
        : "r"(a[0]), "r"(a[1]), "r"(a[2]), "r"(a[3]), "r"(b0), "r"(b1));
}

// ---------------------------------------------------------------------------
// bf16 tensor-core GEMM: D[M][N] = A[M][K] * B^T (+bias) (+res)
//   A: bf16 [M][K] row-major.
//   TRB=0: B bf16 [N][K]. TRB=1: B bf16 [K][N] (ldmatrix.trans).
// Block tile 128x128x64, 128 thr = 4 warps (2x2), WARP TILE 64x64, m16n8k16.
// 3-stage cp.async pipeline, one __syncthreads per chunk, wait_group 1.
// ---------------------------------------------------------------------------
#define BM 128
#define BN 128
#define BK 64
#define ASTR 144
#define BSTR_N 144
#define BSTR_T 272
#define ASTAGE (BM * ASTR)        // 18432
#define BSTAGE_N (BN * BSTR_N)    // 18432
#define BSTAGE_T (BK * BSTR_T)    // 17408
#define SMEM3_NT (3 * (ASTAGE + BSTAGE_N))   // 110592
#define SMEM3_TR (3 * (ASTAGE + BSTAGE_T))   // 107520

template<int BIAS_MODE, bool RES, bool TRB, bool OUTBF>
__global__ __launch_bounds__(128, 2) void gemm_bf16_tc(
    const __nv_bfloat16* __restrict__ A, const __nv_bfloat16* __restrict__ B,
    void* __restrict__ Cv,
    const float* __restrict__ bias, const float* __restrict__ res,
    int K, int lda, int ldb, int ldc,
    long long sA, long long sB, long long sC, long long sR)
{
    extern __shared__ char smem[];
    constexpr int BSTAGE = TRB ? BSTAGE_T : BSTAGE_N;
    const uint32_t sbA = smem_u32(smem);
    const uint32_t sbB = sbA + 3 * ASTAGE;

    const int tid  = threadIdx.x;
    const int wid  = tid >> 5;
    const int lane = tid & 31;
    const int g    = lane >> 2;
    const int tig  = lane & 3;
    const int sub  = lane >> 3;      // 0..3 ldmatrix subtile id
    const int r8   = lane & 7;
    const int m_w  = (wid >> 1) * 64;
    const int n_w  = (wid & 1) * 64;
    const int m0   = blockIdx.y * BM;
    const int n0   = blockIdx.x * BN;
    const int z    = blockIdx.z;

    const __nv_bfloat16* Ab = A + (long long)z * sA + (long long)m0 * lda;
    const __nv_bfloat16* Bb = TRB ? (B + (long long)z * sB + n0)
                                  : (B + (long long)z * sB + (long long)n0 * ldb);

    float acc[4][8][4];
    #pragma unroll
    for (int i = 0; i < 4; i++)
        #pragma unroll
        for (int j = 0; j < 8; j++)
            #pragma unroll
            for (int r = 0; r < 4; r++) acc[i][j][r] = 0.f;

    const int nk = K / BK;

    auto load = [&](int ks, int buf) {
        const uint32_t ab = sbA + buf * ASTAGE;
        const uint32_t bb = sbB + buf * BSTAGE;
        #pragma unroll
        for (int it = 0; it < 8; it++) {           // A: 1024 x 16B chunks
            int s = tid + it * 128;
            int r = s >> 3, c = s & 7;
            cpasync16(ab + r * ASTR + c * 16,
                      Ab + (long long)r * lda + ks * BK + c * 8);
        }
        if (!TRB) {
            #pragma unroll
            for (int it = 0; it < 8; it++) {       // B: 128 n-rows x 8 chunks
                int s = tid + it * 128;
                int r = s >> 3, c = s & 7;
                cpasync16(bb + r * BSTR_N + c * 16,
                          Bb + (long long)r * ldb + ks * BK + c * 8);
            }
        } else {
            #pragma unroll
            for (int it = 0; it < 8; it++) {       // B: 64 k-rows x 16 chunks
                int s = tid + it * 128;
                int r = s >> 4, c = s & 15;
                cpasync16(bb + r * BSTR_T + c * 16,
                          Bb + (long long)(ks * BK + r) * ldb + c * 8);
            }
        }
        asm volatile("cp.async.commit_group;");
    };

    load(0, 0);
    if (nk > 1) load(1, 1);

    #pragma unroll 1
    for (int ks = 0; ks < nk; ks++) {
        const int buf = ks % 3;
        if (ks + 1 < nk) asm volatile("cp.async.wait_group 1;");
        else             asm volatile("cp.async.wait_group 0;");
        __syncthreads();
        if (ks + 2 < nk) load(ks + 2, (ks + 2) % 3);

        const uint32_t ab = sbA + buf * ASTAGE;
        const uint32_t bb = sbB + buf * BSTAGE;

        #pragma unroll
        for (int kk = 0; kk < 4; kk++) {
            uint32_t af[4][4];
            #pragma unroll
            for (int i = 0; i < 4; i++) {
                uint32_t addr = ab + (m_w + 16 * i + (sub & 1) * 8 + r8) * ASTR
                              + kk * 32 + (sub >> 1) * 16;
                ldsm4(af[i], addr);
            }
            uint32_t bf[8][2];
            #pragma unroll
            for (int jj = 0; jj < 4; jj++) {
                uint32_t t[4];
                if (!TRB) {
                    uint32_t addr = bb + (n_w + 16 * jj + (sub >> 1) * 8 + r8) * BSTR_N
                                  + kk * 32 + (sub & 1) * 16;
                    ldsm4(t, addr);
                } else {
                    uint32_t addr = bb + (kk * 16 + (sub & 1) * 8 + r8) * BSTR_T
                                  + (n_w + 16 * jj + (sub >> 1) * 8) * 2;
                    ldsm4t(t, addr);
                }
                bf[2 * jj][0] = t[0]; bf[2 * jj][1] = t[1];
                bf[2 * jj + 1][0] = t[2]; bf[2 * jj + 1][1] = t[3];
            }
            #pragma unroll
            for (int i = 0; i < 4; i++)
                #pragma unroll
                for (int j = 0; j < 8; j++)
                    mma_bf16(acc[i][j], af[i], bf[j][0], bf[j][1]);
        }
    }

    // epilogue
    if (OUTBF) {
        __nv_bfloat16* C = (__nv_bfloat16*)Cv + (long long)z * sC;
        #pragma unroll
        for (int i = 0; i < 4; i++) {
            int r0 = m0 + m_w + 16 * i + g;
            int r1 = r0 + 8;
            float bm0 = (BIAS_MODE == 1) ? bias[r0] : 0.f;
            float bm1 = (BIAS_MODE == 1) ? bias[r1] : 0.f;
            #pragma unroll
            for (int j = 0; j < 8; j++) {
                int col = n0 + n_w + 8 * j + 2 * tig;
                float bn0 = 0.f, bn1 = 0.f;
                if (BIAS_MODE == 2) { bn0 = bias[col]; bn1 = bias[col + 1]; }
                float2 v0 = make_float2(acc[i][j][0] + bm0 + bn0,
                                        acc[i][j][1] + bm0 + bn1);
                float2 v1 = make_float2(acc[i][j][2] + bm1 + bn0,
                                        acc[i][j][3] + bm1 + bn1);
                *(__nv_bfloat162*)&C[(long long)r0 * ldc + col] = __float22bfloat162_rn(v0);
                *(__nv_bfloat162*)&C[(long long)r1 * ldc + col] = __float22bfloat162_rn(v1);
            }
        }
    } else {
        float* C = (float*)Cv + (long long)z * sC;
        const float* Rb = RES ? res + (long long)z * sR : nullptr;
        #pragma unroll
        for (int i = 0; i < 4; i++) {
            int r0 = m0 + m_w + 16 * i + g;
            int r1 = r0 + 8;
            float bm0 = (BIAS_MODE == 1) ? bias[r0] : 0.f;
            float bm1 = (BIAS_MODE == 1) ? bias[r1] : 0.f;
            #pragma unroll
            for (int j = 0; j < 8; j++) {
                int col = n0 + n_w + 8 * j + 2 * tig;
                long long o0 = (long long)r0 * ldc + col;
                long long o1 = (long long)r1 * ldc + col;
                float2 v0 = make_float2(acc[i][j][0] + bm0, acc[i][j][1] + bm0);
                float2 v1 = make_float2(acc[i][j][2] + bm1, acc[i][j][3] + bm1);
                if (RES) {
                    float2 a0 = *(const float2*)&Rb[o0];
                    float2 a1 = *(const float2*)&Rb[o1];
                    v0.x += a0.x; v0.y += a0.y;
                    v1.x += a1.x; v1.y += a1.y;
                }
                *(float2*)&C[o0] = v0;
                *(float2*)&C[o1] = v1;
            }
        }
    }
}

// ---------------------------------------------------------------------------
// Weight/bias prep: concat(wq*s, wk, wv) -> bf16; wo -> bf16; bias concat.
// ---------------------------------------------------------------------------
__global__ __launch_bounds__(256) void prep_weights(
    const float* __restrict__ wq, const float* __restrict__ wk,
    const float* __restrict__ wv, const float* __restrict__ wo,
    const float* __restrict__ bq, const float* __restrict__ bk,
    const float* __restrict__ bv,
    __nv_bfloat16* __restrict__ wqkv, __nv_bfloat16* __restrict__ wob,
    float* __restrict__ bqkv)
{
    const float scale = 0.044194173824159216f;   // 512^-0.5
    int idx = blockIdx.x * 256 + threadIdx.x;
    if (idx < NQKV * CCH) {
        int row = idx >> 9, col = idx & 511;
        int which = row >> 9, rr = row & 511;
        float v = which == 0 ? wq[rr * 512 + col] * scale
                : which == 1 ? wk[rr * 512 + col]
                             : wv[rr * 512 + col];
        wqkv[idx] = __float2bfloat16_rn(v);
        if (idx < NQKV) {
            int w2 = idx >> 9, r2 = idx & 511;
            bqkv[idx] = w2 == 0 ? bq[r2] * scale : w2 == 1 ? bk[r2] : bv[r2];
        }
    } else {
        int j = idx - NQKV * CCH;
        wob[j] = __float2bfloat16_rn(wo[j]);
    }
}

// ---------------------------------------------------------------------------
// GroupNorm stats + apply-with-transpose (bf16 out)
// ---------------------------------------------------------------------------
__global__ __launch_bounds__(256) void gn_stats_kernel(
    const float* __restrict__ x, float* __restrict__ stat)
{
    const int bg = blockIdx.x;
    const long long base = (long long)bg * 65536;
    const int t = threadIdx.x;
    float s = 0.f, ss = 0.f;
    #pragma unroll 8
    for (int i = t; i < 65536; i += 256) {
        float v = x[base + i];
        s += v; ss += v * v;
    }
    #pragma unroll
    for (int off = 16; off; off >>= 1) {
        s  += __shfl_down_sync(0xffffffffu, s,  off);
        ss += __shfl_down_sync(0xffffffffu, ss, off);
    }
    __shared__ float shs[8], shss[8];
    int wid = t >> 5, lane = t & 31;
    if (lane == 0) { shs[wid] = s; shss[wid] = ss; }
    __syncthreads();
    if (t == 0) {
        float ts = 0.f, tss = 0.f;
        #pragma unroll
        for (int i = 0; i < 8; i++) { ts += shs[i]; tss += shss[i]; }
        float mean = ts * (1.f / 65536.f);
        float var  = tss * (1.f / 65536.f) - mean * mean;
        stat[2 * bg]     = mean;
        stat[2 * bg + 1] = rsqrtf(var + GEPS);
    }
}

__global__ __launch_bounds__(256) void gn_apply_t_kernel(
    const float* __restrict__ x, const float* __restrict__ w,
    const float* __restrict__ b, const float* __restrict__ stat,
    __nv_bfloat16* __restrict__ ht)
{
    __shared__ float tile[32][33];
    const int p0 = blockIdx.x * 32;
    const int c0 = blockIdx.y * 32;
    const int bb = blockIdx.z;
    const int tx = threadIdx.x, ty = threadIdx.y;   // (32, 8)
    const long long xb = (long long)bb * CN;

    #pragma unroll
    for (int r = 0; r < 4; r++) {
        int cl = ty + 8 * r;
        tile[cl][tx] = x[xb + (long long)(c0 + cl) * NPIX + p0 + tx];
    }
    __syncthreads();
    const int c = c0 + tx;
    const int gidx = c >> 4;
    const float mean = stat[2 * (bb * 32 + gidx)];
    const float rstd = stat[2 * (bb * 32 + gidx) + 1];
    const float sc = rstd * w[c];
    const float sh = b[c] - mean * sc;
    #pragma unroll
    for (int r = 0; r < 4; r++) {
        int pl = ty + 8 * r;
        float v = tile[tx][pl] * sc + sh;
        ht[xb + (long long)(p0 + pl) * CCH + c] = __float2bfloat16_rn(v);
    }
}

// ---------------------------------------------------------------------------
// Row softmax: fp32 scores in, bf16 probs out (vectorized)
// ---------------------------------------------------------------------------
__global__ __launch_bounds__(256) void softmax_kernel(
    const float* __restrict__ attn, __nv_bfloat16* __restrict__ p)
{
    const float4* s = (const float4*)(attn + (long long)blockIdx.x * NPIX);
    __nv_bfloat162* po = (__nv_bfloat162*)(p + (long long)blockIdx.x * NPIX);
    const int t = threadIdx.x;
    float4 v[4];
    float mx = -1e30f;
    #pragma unroll
    for (int i = 0; i < 4; i++) {
        v[i] = s[t + i * 256];
        mx = fmaxf(mx, fmaxf(fmaxf(v[i].x, v[i].y), fmaxf(v[i].z, v[i].w)));
    }
    #pragma unroll
    for (int off = 16; off; off >>= 1)
        mx = fmaxf(mx, __shfl_xor_sync(0xffffffffu, mx, off));
    __shared__ float sh[8];
    __shared__ float blk[2];
    int wid = t >> 5, lane = t & 31;
    if (lane == 0) sh[wid] = mx;
    __syncthreads();
    if (t == 0) {
        float m = sh[0];
        #pragma unroll
        for (int i = 1; i < 8; i++) m = fmaxf(m, sh[i]);
        blk[0] = m;
    }
    __syncthreads();
    mx = blk[0];
    float sum = 0.f;
    #pragma unroll
    for (int i = 0; i < 4; i++) {
        v[i].x = __expf(v[i].x - mx); v[i].y = __expf(v[i].y - mx);
        v[i].z = __expf(v[i].z - mx); v[i].w = __expf(v[i].w - mx);
        sum += (v[i].x + v[i].y) + (v[i].z + v[i].w);
    }
    #pragma unroll
    for (int off = 16; off; off >>= 1)
        sum += __shfl_xor_sync(0xffffffffu, sum, off);
    if (lane == 0) sh[wid] = sum;
    __syncthreads();
    if (t == 0) {
        float tot = 0.f;
        #pragma unroll
        for (int i = 0; i < 8; i++) tot += sh[i];
        blk[1] = 1.f / tot;
    }
    __syncthreads();
    const float inv = blk[1];
    #pragma unroll
    for (int i = 0; i < 4; i++) {
        po[2 * (t + i * 256)] =
            __float22bfloat162_rn(make_float2(v[i].x * inv, v[i].y * inv));
        po[2 * (t + i * 256) + 1] =
            __float22bfloat162_rn(make_float2(v[i].z * inv, v[i].w * inv));
    }
}

// ---------------------------------------------------------------------------
extern "C" void kernel_launch(void* const* d_in, const int* in_sizes, int n_in,
                              void* d_out, int out_size)
{
    const float* x    = (const float*)d_in[0];
    const float* gn_w = (const float*)d_in[1];
    const float* gn_b = (const float*)d_in[2];
    const float* wq   = (const float*)d_in[3];
    const float* bq   = (const float*)d_in[4];
    const float* wk   = (const float*)d_in[5];
    const float* bk   = (const float*)d_in[6];
    const float* wv   = (const float*)d_in[7];
    const float* bv   = (const float*)d_in[8];
    const float* wo   = (const float*)d_in[9];
    const float* bo   = (const float*)d_in[10];
    float* out = (float*)d_out;

    __nv_bfloat16 *ht, *qkv, *p, *ot, *wqkv, *wob;
    float *attn, *bqkv, *stat;
    cudaGetSymbolAddress((void**)&ht,   g_ht);
    cudaGetSymbolAddress((void**)&qkv,  g_qkv);
    cudaGetSymbolAddress((void**)&attn, g_attn);
    cudaGetSymbolAddress((void**)&p,    g_p);
    cudaGetSymbolAddress((void**)&ot,   g_ot);
    cudaGetSymbolAddress((void**)&wqkv, g_wqkv);
    cudaGetSymbolAddress((void**)&wob,  g_wo);
    cudaGetSymbolAddress((void**)&bqkv, g_bqkv);
    cudaGetSymbolAddress((void**)&stat, g_stat);

    cudaFuncSetAttribute(gemm_bf16_tc<2, false, false, true >,
        cudaFuncAttributeMaxDynamicSharedMemorySize, SMEM3_NT);
    cudaFuncSetAttribute(gemm_bf16_tc<0, false, false, false>,
        cudaFuncAttributeMaxDynamicSharedMemorySize, SMEM3_NT);
    cudaFuncSetAttribute(gemm_bf16_tc<0, false, true , true >,
        cudaFuncAttributeMaxDynamicSharedMemorySize, SMEM3_TR);
    cudaFuncSetAttribute(gemm_bf16_tc<1, true , false, false>,
        cudaFuncAttributeMaxDynamicSharedMemorySize, SMEM3_NT);

    // 0) weights -> bf16 (scale folded into wq/bq)
    prep_weights<<<(NQKV * CCH + CCH * CCH) / 256, 256>>>(
        wq, wk, wv, wo, bq, bk, bv, wqkv, wob, bqkv);

    // 1) GroupNorm -> hT bf16 [B][pix][C]
    gn_stats_kernel<<<BATCH * 32, 256>>>(x, stat);
    gn_apply_t_kernel<<<dim3(NPIX / 32, CCH / 32, BATCH), dim3(32, 8)>>>(
        x, gn_w, gn_b, stat, ht);

    // 2) fused QKV: qkvT[pix][1536] = hT @ wqkv^T + bqkv[n]
    dim3 gQKV(NQKV / BN, NPIX / BM, BATCH);
    gemm_bf16_tc<2, false, false, true><<<gQKV, 128, SMEM3_NT>>>(
        ht, wqkv, qkv, bqkv, nullptr, CCH, CCH, CCH, NQKV,
        CN, 0, QKVN, 0);

    // 3) S = qT @ kT^T (scale pre-folded), fp32 scores
    dim3 gS(NPIX / BN, NPIX / BM, BATCH);
    gemm_bf16_tc<0, false, false, false><<<gS, 128, SMEM3_NT>>>(
        qkv, qkv + 512, attn, nullptr, nullptr, CCH, NQKV, NQKV, NPIX,
        QKVN, QKVN, NN, 0);

    // 4) softmax -> bf16 probs
    softmax_kernel<<<BATCH * NPIX, 256>>>(attn, p);

    // 5) OT[pix][C] = P @ vT (vT = qkv cols 1024..1535, trans-B)
    dim3 gAV(CCH / BN, NPIX / BM, BATCH);
    gemm_bf16_tc<0, false, true, true><<<gAV, 128, SMEM3_TR>>>(
        p, qkv + 1024, ot, nullptr, nullptr, NPIX, NPIX, NQKV, CCH,
        NN, QKVN, CN, 0);

    // 6) out = x + wo @ OT^T + bo[m] (fp32)
    dim3 gF(NPIX / BN, CCH / BM, BATCH);
    gemm_bf16_tc<1, true, false, false><<<gF, 128, SMEM3_NT>>>(
        wob, ot, out, bo, x, CCH, CCH, CCH, NPIX,
        0, CN, CN, CN);
}

// round 8
// speedup vs baseline: 6.4395x; 1.0664x over previous
#include <cuda_runtime.h>
#include <cuda_bf16.h>
#include <cstdint>

// B=2, C=512, N=4096. out = x + Wo@Attn(GN(x)) + bo, [B,C,H,W] fp32.
#define BATCH 2
#define CCH   512
#define NPIX  4096
#define NQKV  1536
#define GEPS  1e-6f

static const long long CN   = (long long)CCH * NPIX;    // 2M
static const long long NN   = (long long)NPIX * NPIX;   // 16M
static const long long QKVN = (long long)NPIX * NQKV;   // 6M

// scratch (device globals)
__device__ __nv_bfloat16 g_ht [BATCH * NPIX * CCH];             // hT [B][pix][C]
__device__ __nv_bfloat16 g_qkv[(long long)BATCH * NPIX * NQKV]; // [B][pix][q|k|v]
__device__ __nv_bfloat16 g_p  [(long long)BATCH * NPIX * NPIX]; // exp(S) bf16
__device__ __nv_bfloat16 g_ot [BATCH * NPIX * CCH];             // OT [B][pix][C]
__device__ __nv_bfloat16 g_wqkv[NQKV * CCH];                    // concat(wq*s,wk,wv)
__device__ __nv_bfloat16 g_wo [CCH * CCH];
__device__ float         g_bqkv[NQKV];
__device__ float         g_rowsum[BATCH * NPIX];                // softmax denominators
__device__ float         g_stat[BATCH * 32 * 2];

// ---------------------------------------------------------------------------
// PTX helpers
// ---------------------------------------------------------------------------
__device__ __forceinline__ void cpasync16(uint32_t s, const void* g) {
    asm volatile("cp.async.cg.shared.global [%0], [%1], 16;" :: "r"(s), "l"(g));
}
__device__ __forceinline__ uint32_t smem_u32(const void* p) {
    return (uint32_t)__cvta_generic_to_shared(p);
}
__device__ __forceinline__ void ldsm4(uint32_t r[4], uint32_t addr) {
    asm volatile("ldmatrix.sync.aligned.m8n8.x4.shared.b16 {%0,%1,%2,%3}, [%4];"
        : "=r"(r[0]), "=r"(r[1]), "=r"(r[2]), "=r"(r[3]) : "r"(addr));
}
__device__ __forceinline__ void ldsm4t(uint32_t r[4], uint32_t addr) {
    asm volatile("ldmatrix.sync.aligned.m8n8.x4.trans.shared.b16 {%0,%1,%2,%3}, [%4];"
        : "=r"(r[0]), "=r"(r[1]), "=r"(r[2]), "=r"(r[3]) : "r"(addr));
}
__device__ __forceinline__ void mma_bf16(float c[4], const uint32_t a[4],
                                         const uint32_t b0, const uint32_t b1) {
    asm volatile(
        "mma.sync.aligned.m16n8k16.row.col.f32.bf16.bf16.f32 "
        "{%0,%1,%2,%3},{%4,%5,%6,%7},{%8,%9},{%0,%1,%2,%3};"
        : "+f"(c[0]), "+f"(c[1]), "+f"(c[2]), "+f"(c[3])
        : "r"(a[0]), "r"(a[1]), "r"(a[2]), "r"(a[3]), "r"(b0), "r"(b1));
}

// ---------------------------------------------------------------------------
// bf16 tensor-core GEMM: D[M][N] = A[M][K] * B^T
//   A bf16 [M][K]; TRB=0: B bf16 [N][K]; TRB=1: B bf16 [K][N] (ldmatrix.trans)
// Block 128x128x64, 256 thr = 8 warps (2x4), warp tile 64x32, m16n8k16,
// 3-stage cp.async.
// EPI: 1 = bf16 out + bias[n] (aux=bias)            (QKV)
//      2 = expf + bf16 out + rowsum atomics (aux=rowsum, stride sAux)  (S)
//      3 = bf16 out * (1/rowsum[m]) (aux=rowsum, stride sAux)          (AV)
//      4 = fp32 out + bias[m] (aux) + residual (res, stride sR)        (final)
// ---------------------------------------------------------------------------
#define BM 128
#define BN 128
#define BK 64
#define ASTR 144
#define BSTR_N 144
#define BSTR_T 272
#define ASTAGE (BM * ASTR)
#define BSTAGE_N (BN * BSTR_N)
#define BSTAGE_T (BK * BSTR_T)
#define SMEM3_NT (3 * (ASTAGE + BSTAGE_N))   // 110592
#define SMEM3_TR (3 * (ASTAGE + BSTAGE_T))   // 107520

template<int EPI, bool TRB>
__global__ __launch_bounds__(256, 2) void gemm_bf16_tc(
    const __nv_bfloat16* __restrict__ A, const __nv_bfloat16* __restrict__ B,
    void* __restrict__ Cv,
    const float* __restrict__ aux, const float* __restrict__ res,
    int K, int lda, int ldb, int ldc,
    long long sA, long long sB, long long sC, long long sAux, long long sR)
{
    extern __shared__ char smem[];
    constexpr int BSTAGE = TRB ? BSTAGE_T : BSTAGE_N;
    const uint32_t sbA = smem_u32(smem);
    const uint32_t sbB = sbA + 3 * ASTAGE;

    const int tid  = threadIdx.x;
    const int wid  = tid >> 5;
    const int lane = tid & 31;
    const int g    = lane >> 2;
    const int tig  = lane & 3;
    const int sub  = lane >> 3;
    const int r8   = lane & 7;
    const int m_w  = (wid >> 2) * 64;
    const int n_w  = (wid & 3) * 32;
    const int m0   = blockIdx.y * BM;
    const int n0   = blockIdx.x * BN;
    const int z    = blockIdx.z;

    const __nv_bfloat16* Ab = A + (long long)z * sA + (long long)m0 * lda;
    const __nv_bfloat16* Bb = TRB ? (B + (long long)z * sB + n0)
                                  : (B + (long long)z * sB + (long long)n0 * ldb);

    float acc[4][4][4];
    #pragma unroll
    for (int i = 0; i < 4; i++)
        #pragma unroll
        for (int j = 0; j < 4; j++)
            #pragma unroll
            for (int r = 0; r < 4; r++) acc[i][j][r] = 0.f;

    const int nk = K / BK;

    auto load = [&](int ks, int buf) {
        const uint32_t ab = sbA + buf * ASTAGE;
        const uint32_t bb = sbB + buf * BSTAGE;
        #pragma unroll
        for (int it = 0; it < 4; it++) {
            int s = tid + it * 256;
            int r = s >> 3, c = s & 7;
            cpasync16(ab + r * ASTR + c * 16,
                      Ab + (long long)r * lda + ks * BK + c * 8);
        }
        if (!TRB) {
            #pragma unroll
            for (int it = 0; it < 4; it++) {
                int s = tid + it * 256;
                int r = s >> 3, c = s & 7;
                cpasync16(bb + r * BSTR_N + c * 16,
                          Bb + (long long)r * ldb + ks * BK + c * 8);
            }
        } else {
            #pragma unroll
            for (int it = 0; it < 4; it++) {
                int s = tid + it * 256;
                int r = s >> 4, c = s & 15;
                cpasync16(bb + r * BSTR_T + c * 16,
                          Bb + (long long)(ks * BK + r) * ldb + c * 8);
            }
        }
        asm volatile("cp.async.commit_group;");
    };

    load(0, 0);
    if (nk > 1) load(1, 1);

    #pragma unroll 1
    for (int ks = 0; ks < nk; ks++) {
        const int buf = ks % 3;
        if (ks + 1 < nk) asm volatile("cp.async.wait_group 1;");
        else             asm volatile("cp.async.wait_group 0;");
        __syncthreads();
        if (ks + 2 < nk) load(ks + 2, (ks + 2) % 3);

        const uint32_t ab = sbA + buf * ASTAGE;
        const uint32_t bb = sbB + buf * BSTAGE;

        #pragma unroll
        for (int kk = 0; kk < 4; kk++) {
            uint32_t af[4][4];
            #pragma unroll
            for (int i = 0; i < 4; i++) {
                uint32_t addr = ab + (m_w + 16 * i + (sub & 1) * 8 + r8) * ASTR
                              + kk * 32 + (sub >> 1) * 16;
                ldsm4(af[i], addr);
            }
            uint32_t bf[4][2];
            #pragma unroll
            for (int jj = 0; jj < 2; jj++) {
                uint32_t t[4];
                if (!TRB) {
                    uint32_t addr = bb + (n_w + 16 * jj + (sub >> 1) * 8 + r8) * BSTR_N
                                  + kk * 32 + (sub & 1) * 16;
                    ldsm4(t, addr);
                } else {
                    uint32_t addr = bb + (kk * 16 + (sub & 1) * 8 + r8) * BSTR_T
                                  + (n_w + 16 * jj + (sub >> 1) * 8) * 2;
                    ldsm4t(t, addr);
                }
                bf[2 * jj][0] = t[0]; bf[2 * jj][1] = t[1];
                bf[2 * jj + 1][0] = t[2]; bf[2 * jj + 1][1] = t[3];
            }
            #pragma unroll
            for (int i = 0; i < 4; i++)
                #pragma unroll
                for (int j = 0; j < 4; j++)
                    mma_bf16(acc[i][j], af[i], bf[j][0], bf[j][1]);
        }
    }

    // ------------------------------ epilogues ------------------------------
    if (EPI == 1) {           // bf16 out + bias[n]
        __nv_bfloat16* C = (__nv_bfloat16*)Cv + (long long)z * sC;
        #pragma unroll
        for (int i = 0; i < 4; i++) {
            int r0 = m0 + m_w + 16 * i + g, r1 = r0 + 8;
            #pragma unroll
            for (int j = 0; j < 4; j++) {
                int col = n0 + n_w + 8 * j + 2 * tig;
                float bn0 = aux[col], bn1 = aux[col + 1];
                *(__nv_bfloat162*)&C[(long long)r0 * ldc + col] =
                    __float22bfloat162_rn(make_float2(acc[i][j][0] + bn0,
                                                      acc[i][j][1] + bn1));
                *(__nv_bfloat162*)&C[(long long)r1 * ldc + col] =
                    __float22bfloat162_rn(make_float2(acc[i][j][2] + bn0,
                                                      acc[i][j][3] + bn1));
            }
        }
    } else if (EPI == 2) {    // expf, bf16 out, rowsum atomics
        __nv_bfloat16* C = (__nv_bfloat16*)Cv + (long long)z * sC;
        float* rs = (float*)aux + (long long)z * sAux;
        #pragma unroll
        for (int i = 0; i < 4; i++) {
            int r0 = m0 + m_w + 16 * i + g, r1 = r0 + 8;
            float s0 = 0.f, s1 = 0.f;
            #pragma unroll
            for (int j = 0; j < 4; j++) {
                int col = n0 + n_w + 8 * j + 2 * tig;
                float e0 = __expf(acc[i][j][0]);
                float e1 = __expf(acc[i][j][1]);
                float e2 = __expf(acc[i][j][2]);
                float e3 = __expf(acc[i][j][3]);
                s0 += e0 + e1; s1 += e2 + e3;
                *(__nv_bfloat162*)&C[(long long)r0 * ldc + col] =
                    __float22bfloat162_rn(make_float2(e0, e1));
                *(__nv_bfloat162*)&C[(long long)r1 * ldc + col] =
                    __float22bfloat162_rn(make_float2(e2, e3));
            }
            s0 += __shfl_xor_sync(0xffffffffu, s0, 1);
            s0 += __shfl_xor_sync(0xffffffffu, s0, 2);
            s1 += __shfl_xor_sync(0xffffffffu, s1, 1);
            s1 += __shfl_xor_sync(0xffffffffu, s1, 2);
            if (tig == 0) {
                atomicAdd(&rs[r0], s0);
                atomicAdd(&rs[r1], s1);
            }
        }
    } else if (EPI == 3) {    // bf16 out scaled by 1/rowsum[m]
        __nv_bfloat16* C = (__nv_bfloat16*)Cv + (long long)z * sC;
        const float* rs = aux + (long long)z * sAux;
        #pragma unroll
        for (int i = 0; i < 4; i++) {
            int r0 = m0 + m_w + 16 * i + g, r1 = r0 + 8;
            float i0 = 1.f / rs[r0];
            float i1 = 1.f / rs[r1];
            #pragma unroll
            for (int j = 0; j < 4; j++) {
                int col = n0 + n_w + 8 * j + 2 * tig;
                *(__nv_bfloat162*)&C[(long long)r0 * ldc + col] =
                    __float22bfloat162_rn(make_float2(acc[i][j][0] * i0,
                                                      acc[i][j][1] * i0));
                *(__nv_bfloat162*)&C[(long long)r1 * ldc + col] =
                    __float22bfloat162_rn(make_float2(acc[i][j][2] * i1,
                                                      acc[i][j][3] * i1));
            }
        }
    } else {                  // EPI == 4: fp32 out + bias[m] + residual
        float* C = (float*)Cv + (long long)z * sC;
        const float* Rb = res + (long long)z * sR;
        #pragma unroll
        for (int i = 0; i < 4; i++) {
            int r0 = m0 + m_w + 16 * i + g, r1 = r0 + 8;
            float bm0 = aux[r0], bm1 = aux[r1];
            #pragma unroll
            for (int j = 0; j < 4; j++) {
                int col = n0 + n_w + 8 * j + 2 * tig;
                long long o0 = (long long)r0 * ldc + col;
                long long o1 = (long long)r1 * ldc + col;
                float2 a0 = *(const float2*)&Rb[o0];
                float2 a1 = *(const float2*)&Rb[o1];
                float2 v0 = make_float2(acc[i][j][0] + bm0 + a0.x,
                                        acc[i][j][1] + bm0 + a0.y);
                float2 v1 = make_float2(acc[i][j][2] + bm1 + a1.x,
                                        acc[i][j][3] + bm1 + a1.y);
                *(float2*)&C[o0] = v0;
                *(float2*)&C[o1] = v1;
            }
        }
    }
}

// ---------------------------------------------------------------------------
// zero rowsum (deterministic per launch)
// ---------------------------------------------------------------------------
__global__ __launch_bounds__(256) void zero_rowsum(float* __restrict__ rs)
{
    rs[blockIdx.x * 256 + threadIdx.x] = 0.f;
}

// ---------------------------------------------------------------------------
// Weight/bias prep: concat(wq*s, wk, wv) -> bf16; wo -> bf16; bias concat.
// ---------------------------------------------------------------------------
__global__ __launch_bounds__(256) void prep_weights(
    const float* __restrict__ wq, const float* __restrict__ wk,
    const float* __restrict__ wv, const float* __restrict__ wo,
    const float* __restrict__ bq, const float* __restrict__ bk,
    const float* __restrict__ bv,
    __nv_bfloat16* __restrict__ wqkv, __nv_bfloat16* __restrict__ wob,
    float* __restrict__ bqkv)
{
    const float scale = 0.044194173824159216f;   // 512^-0.5
    int idx = blockIdx.x * 256 + threadIdx.x;
    if (idx < NQKV * CCH) {
        int row = idx >> 9, col = idx & 511;
        int which = row >> 9, rr = row & 511;
        float v = which == 0 ? wq[rr * 512 + col] * scale
                : which == 1 ? wk[rr * 512 + col]
                             : wv[rr * 512 + col];
        wqkv[idx] = __float2bfloat16_rn(v);
        if (idx < NQKV) {
            int w2 = idx >> 9, r2 = idx & 511;
            bqkv[idx] = w2 == 0 ? bq[r2] * scale : w2 == 1 ? bk[r2] : bv[r2];
        }
    } else {
        int j = idx - NQKV * CCH;
        wob[j] = __float2bfloat16_rn(wo[j]);
    }
}

// ---------------------------------------------------------------------------
// GroupNorm stats + apply-with-transpose (bf16 out)
// ---------------------------------------------------------------------------
__global__ __launch_bounds__(256) void gn_stats_kernel(
    const float* __restrict__ x, float* __restrict__ stat)
{
    const int bg = blockIdx.x;
    const long long base = (long long)bg * 65536;
    const int t = threadIdx.x;
    float s = 0.f, ss = 0.f;
    #pragma unroll 8
    for (int i = t; i < 65536; i += 256) {
        float v = x[base + i];
        s += v; ss += v * v;
    }
    #pragma unroll
    for (int off = 16; off; off >>= 1) {
        s  += __shfl_down_sync(0xffffffffu, s,  off);
        ss += __shfl_down_sync(0xffffffffu, ss, off);
    }
    __shared__ float shs[8], shss[8];
    int wid = t >> 5, lane = t & 31;
    if (lane == 0) { shs[wid] = s; shss[wid] = ss; }
    __syncthreads();
    if (t == 0) {
        float ts = 0.f, tss = 0.f;
        #pragma unroll
        for (int i = 0; i < 8; i++) { ts += shs[i]; tss += shss[i]; }
        float mean = ts * (1.f / 65536.f);
        float var  = tss * (1.f / 65536.f) - mean * mean;
        stat[2 * bg]     = mean;
        stat[2 * bg + 1] = rsqrtf(var + GEPS);
    }
}

__global__ __launch_bounds__(256) void gn_apply_t_kernel(
    const float* __restrict__ x, const float* __restrict__ w,
    const float* __restrict__ b, const float* __restrict__ stat,
    __nv_bfloat16* __restrict__ ht)
{
    __shared__ float tile[32][33];
    const int p0 = blockIdx.x * 32;
    const int c0 = blockIdx.y * 32;
    const int bb = blockIdx.z;
    const int tx = threadIdx.x, ty = threadIdx.y;   // (32, 8)
    const long long xb = (long long)bb * CN;

    #pragma unroll
    for (int r = 0; r < 4; r++) {
        int cl = ty + 8 * r;
        tile[cl][tx] = x[xb + (long long)(c0 + cl) * NPIX + p0 + tx];
    }
    __syncthreads();
    const int c = c0 + tx;
    const int gidx = c >> 4;
    const float mean = stat[2 * (bb * 32 + gidx)];
    const float rstd = stat[2 * (bb * 32 + gidx) + 1];
    const float sc = rstd * w[c];
    const float sh = b[c] - mean * sc;
    #pragma unroll
    for (int r = 0; r < 4; r++) {
        int pl = ty + 8 * r;
        float v = tile[tx][pl] * sc + sh;
        ht[xb + (long long)(p0 + pl) * CCH + c] = __float2bfloat16_rn(v);
    }
}

// ---------------------------------------------------------------------------
extern "C" void kernel_launch(void* const* d_in, const int* in_sizes, int n_in,
                              void* d_out, int out_size)
{
    const float* x    = (const float*)d_in[0];
    const float* gn_w = (const float*)d_in[1];
    const float* gn_b = (const float*)d_in[2];
    const float* wq   = (const float*)d_in[3];
    const float* bq   = (const float*)d_in[4];
    const float* wk   = (const float*)d_in[5];
    const float* bk   = (const float*)d_in[6];
    const float* wv   = (const float*)d_in[7];
    const float* bv   = (const float*)d_in[8];
    const float* wo   = (const float*)d_in[9];
    const float* bo   = (const float*)d_in[10];
    float* out = (float*)d_out;

    __nv_bfloat16 *ht, *qkv, *p, *ot, *wqkv, *wob;
    float *bqkv, *stat, *rowsum;
    cudaGetSymbolAddress((void**)&ht,     g_ht);
    cudaGetSymbolAddress((void**)&qkv,    g_qkv);
    cudaGetSymbolAddress((void**)&p,      g_p);
    cudaGetSymbolAddress((void**)&ot,     g_ot);
    cudaGetSymbolAddress((void**)&wqkv,   g_wqkv);
    cudaGetSymbolAddress((void**)&wob,    g_wo);
    cudaGetSymbolAddress((void**)&bqkv,   g_bqkv);
    cudaGetSymbolAddress((void**)&stat,   g_stat);
    cudaGetSymbolAddress((void**)&rowsum, g_rowsum);

    cudaFuncSetAttribute(gemm_bf16_tc<1, false>,
        cudaFuncAttributeMaxDynamicSharedMemorySize, SMEM3_NT);
    cudaFuncSetAttribute(gemm_bf16_tc<2, false>,
        cudaFuncAttributeMaxDynamicSharedMemorySize, SMEM3_NT);
    cudaFuncSetAttribute(gemm_bf16_tc<3, true>,
        cudaFuncAttributeMaxDynamicSharedMemorySize, SMEM3_TR);
    cudaFuncSetAttribute(gemm_bf16_tc<4, false>,
        cudaFuncAttributeMaxDynamicSharedMemorySize, SMEM3_NT);

    // 0) zero softmax denominators; prep weights
    zero_rowsum<<<BATCH * NPIX / 256, 256>>>(rowsum);
    prep_weights<<<(NQKV * CCH + CCH * CCH) / 256, 256>>>(
        wq, wk, wv, wo, bq, bk, bv, wqkv, wob, bqkv);

    // 1) GroupNorm -> hT bf16 [B][pix][C]
    gn_stats_kernel<<<BATCH * 32, 256>>>(x, stat);
    gn_apply_t_kernel<<<dim3(NPIX / 32, CCH / 32, BATCH), dim3(32, 8)>>>(
        x, gn_w, gn_b, stat, ht);

    // 2) fused QKV: qkvT[pix][1536] = hT @ wqkv^T + bqkv[n]
    dim3 gQKV(NQKV / BN, NPIX / BM, BATCH);
    gemm_bf16_tc<1, false><<<gQKV, 256, SMEM3_NT>>>(
        ht, wqkv, qkv, bqkv, nullptr, CCH, CCH, CCH, NQKV,
        CN, 0, QKVN, 0, 0);

    // 3) P = exp(qT @ kT^T) (scale pre-folded) -> bf16, rowsum accumulated
    dim3 gS(NPIX / BN, NPIX / BM, BATCH);
    gemm_bf16_tc<2, false><<<gS, 256, SMEM3_NT>>>(
        qkv, qkv + 512, p, rowsum, nullptr, CCH, NQKV, NQKV, NPIX,
        QKVN, QKVN, NN, NPIX, 0);

    // 4) OT[pix][C] = (P @ vT) / rowsum[pix]
    dim3 gAV(CCH / BN, NPIX / BM, BATCH);
    gemm_bf16_tc<3, true><<<gAV, 256, SMEM3_TR>>>(
        p, qkv + 1024, ot, rowsum, nullptr, NPIX, NPIX, NQKV, CCH,
        NN, QKVN, CN, NPIX, 0);

    // 5) out = x + wo @ OT^T + bo[m]  (fp32)
    dim3 gF(NPIX / BN, CCH / BM, BATCH);
    gemm_bf16_tc<4, false><<<gF, 256, SMEM3_NT>>>(
        wob, ot, out, bo, x, CCH, CCH, CCH, NPIX,
        0, CN, CN, 0, CN);
}